// round 2
// baseline (speedup 1.0000x reference)
#include <cuda_runtime.h>
#include <cuda_fp16.h>
#include <math.h>

// Problem constants
#define BB 1024
#define SS 128      // N*HIST
#define DD 256
#define EE 128
#define NHH 8
#define HDD 32
#define INV_SQRT_HD 0.17677669529663687f

// ---------------- device scratch (allowed: __device__ globals) ----------------
__device__ __align__(16) __half g_K[(size_t)BB * SS * DD];   // 64 MB
__device__ __align__(16) __half g_V[(size_t)BB * SS * DD];   // 64 MB
__device__ __align__(16) float  g_a [BB * DD];               // gate*(1+tanh(scale))
__device__ __align__(16) float  g_s2[BB * DD];               // gate*shift
__device__ __align__(16) float  g_eb[BB * NHH];
__device__ __align__(16) float  g_hs[BB * NHH];              // (1+tanh(head))*inv_sqrt(HD)

// ---------------- f32x2 helpers ----------------
__device__ __forceinline__ unsigned long long splat2(float x) {
    unsigned long long r;
    asm("mov.b64 %0, {%1, %1};" : "=l"(r) : "f"(x));
    return r;
}
__device__ __forceinline__ void ffma2(unsigned long long& a,
                                      unsigned long long x,
                                      unsigned long long w) {
    asm("fma.rn.f32x2 %0, %1, %2, %0;" : "+l"(a) : "l"(x), "l"(w));
}
union F2U { unsigned long long u; float2 f; };

// =====================================================================
// Kernel 1: edge MLPs.  grid 128 blocks x 256 threads, 8 batches/block.
// =====================================================================
__global__ void __launch_bounds__(256)
edge_kernel(const float* __restrict__ EF,
            const float* __restrict__ Wgate, const float* __restrict__ bgate,
            const float* __restrict__ Wscale, const float* __restrict__ bscale,
            const float* __restrict__ Wshift, const float* __restrict__ bshift,
            const float* __restrict__ Wbias, const float* __restrict__ bbias,
            const float* __restrict__ Whead, const float* __restrict__ bhead)
{
    __shared__ float ef[8][EE];
    const int b0 = blockIdx.x * 8;
    const int t  = threadIdx.x;

    #pragma unroll
    for (int i = 0; i < 4; i++) {
        int s  = t + i * 256;        // 0..1023
        int bi = s >> 7, e = s & 127;
        ef[bi][e] = EF[(size_t)(b0 + bi) * EE + e];
    }
    __syncthreads();

    // gate / scale / shift for all 8 batches, channel c = t
    {
        const int c = t;
        float ag[8], as[8], ah[8];
        const float bg = bgate[c], bs = bscale[c], bh = bshift[c];
        #pragma unroll
        for (int i = 0; i < 8; i++) { ag[i] = bg; as[i] = bs; ah[i] = bh; }
        for (int e = 0; e < EE; e++) {
            const float wg = Wgate[e * DD + c];
            const float ws = Wscale[e * DD + c];
            const float wh = Wshift[e * DD + c];
            #pragma unroll
            for (int i = 0; i < 8; i++) {
                const float f = ef[i][e];
                ag[i] += f * wg; as[i] += f * ws; ah[i] += f * wh;
            }
        }
        #pragma unroll
        for (int i = 0; i < 8; i++) {
            const float gate = 1.0f / (1.0f + expf(-ag[i]));
            const float sc   = tanhf(as[i]);
            g_a [(b0 + i) * DD + c] = gate * (1.0f + sc);
            g_s2[(b0 + i) * DD + c] = gate * ah[i];
        }
    }

    // edge_bias and head_scale (8 heads x 8 batches each)
    if (t < 64) {
        const int bi = t >> 3, h = t & 7;
        float acc = bbias[h];
        for (int e = 0; e < EE; e++) acc += ef[bi][e] * Wbias[e * NHH + h];
        g_eb[(b0 + bi) * NHH + h] = acc;
    } else if (t < 128) {
        const int u = t - 64;
        const int bi = u >> 3, h = u & 7;
        float acc = bhead[h];
        for (int e = 0; e < EE; e++) acc += ef[bi][e] * Whead[e * NHH + h];
        g_hs[(b0 + bi) * NHH + h] = (1.0f + tanhf(acc)) * INV_SQRT_HD;
    }
}

// =====================================================================
// Kernel 2: K/V projection GEMM.
//   grid (4, 1024): blockIdx.y = batch (128 rows), blockIdx.x = 128-col tile
//   of the 512-wide concat [Wk | Wv].  256 threads, 8x8 micro-tiles, f32x2.
//   Epilogue: +bias, V gating, fp16 store.
// =====================================================================
__global__ void __launch_bounds__(256, 2)
gemm_kv_kernel(const float* __restrict__ X,
               const float* __restrict__ Wk, const float* __restrict__ bk,
               const float* __restrict__ Wv, const float* __restrict__ bv)
{
    const int b  = blockIdx.y;
    const int nb = blockIdx.x;            // 0,1 -> K ; 2,3 -> V
    const bool isK = (nb < 2);
    const int colbase = (nb & 1) * 128;   // within the 256-wide W
    const float* __restrict__ W = isK ? Wk : Wv;

    __shared__ __align__(16) float Xs[2][16][128];
    __shared__ __align__(16) float Ws[2][16][128];

    const int t  = threadIdx.x;
    const int tx = t & 15, ty = t >> 4;

    const float4* X4 = reinterpret_cast<const float4*>(X + (size_t)b * SS * DD);

    unsigned long long acc[8][4];
    #pragma unroll
    for (int r = 0; r < 8; r++)
        #pragma unroll
        for (int c = 0; c < 4; c++) acc[r][c] = 0ull;

    float4 rx[2], rw[2];

    // ---- load chunk 0 ----
    #pragma unroll
    for (int i = 0; i < 2; i++) {
        int s = t + i * 256;
        int kq = s & 3, row = s >> 2;
        rx[i] = X4[row * 64 + 0 + kq];
        int col4 = s & 31, kk = s >> 5;
        rw[i] = reinterpret_cast<const float4*>(W + (size_t)kk * DD + colbase)[col4];
    }
    #pragma unroll
    for (int i = 0; i < 2; i++) {
        int s = t + i * 256;
        int kq = s & 3, row = s >> 2;
        Xs[0][kq * 4 + 0][row] = rx[i].x;
        Xs[0][kq * 4 + 1][row] = rx[i].y;
        Xs[0][kq * 4 + 2][row] = rx[i].z;
        Xs[0][kq * 4 + 3][row] = rx[i].w;
        int col4 = s & 31, kk = s >> 5;
        *reinterpret_cast<float4*>(&Ws[0][kk][col4 * 4]) = rw[i];
    }
    __syncthreads();

    for (int ch = 0; ch < 16; ch++) {
        const int cur = ch & 1;
        if (ch < 15) {
            const int k0q = (ch + 1) * 4;
            const int k0  = (ch + 1) * 16;
            #pragma unroll
            for (int i = 0; i < 2; i++) {
                int s = t + i * 256;
                int kq = s & 3, row = s >> 2;
                rx[i] = X4[row * 64 + k0q + kq];
                int col4 = s & 31, kk = s >> 5;
                rw[i] = reinterpret_cast<const float4*>(W + (size_t)(k0 + kk) * DD + colbase)[col4];
            }
        }
        #pragma unroll
        for (int kk = 0; kk < 16; kk++) {
            const float4 xa = *reinterpret_cast<const float4*>(&Xs[cur][kk][ty * 8]);
            const float4 xb = *reinterpret_cast<const float4*>(&Xs[cur][kk][ty * 8 + 4]);
            unsigned long long wp[4];
            #pragma unroll
            for (int c = 0; c < 4; c++)
                wp[c] = *reinterpret_cast<const unsigned long long*>(&Ws[cur][kk][tx * 8 + 2 * c]);
            unsigned long long xs[8];
            xs[0] = splat2(xa.x); xs[1] = splat2(xa.y); xs[2] = splat2(xa.z); xs[3] = splat2(xa.w);
            xs[4] = splat2(xb.x); xs[5] = splat2(xb.y); xs[6] = splat2(xb.z); xs[7] = splat2(xb.w);
            #pragma unroll
            for (int r = 0; r < 8; r++)
                #pragma unroll
                for (int c = 0; c < 4; c++)
                    ffma2(acc[r][c], xs[r], wp[c]);
        }
        if (ch < 15) {
            const int nxt = cur ^ 1;
            #pragma unroll
            for (int i = 0; i < 2; i++) {
                int s = t + i * 256;
                int kq = s & 3, row = s >> 2;
                Xs[nxt][kq * 4 + 0][row] = rx[i].x;
                Xs[nxt][kq * 4 + 1][row] = rx[i].y;
                Xs[nxt][kq * 4 + 2][row] = rx[i].z;
                Xs[nxt][kq * 4 + 3][row] = rx[i].w;
                int col4 = s & 31, kk = s >> 5;
                *reinterpret_cast<float4*>(&Ws[nxt][kk][col4 * 4]) = rw[i];
            }
            __syncthreads();
        }
    }

    // ---- epilogue ----
    const int row0 = ty * 8;
    const int oc0  = colbase + tx * 8;      // column within 0..255 of K or V
    float bias[8];
    {
        const float* bsrc = isK ? bk : bv;
        *reinterpret_cast<float4*>(&bias[0]) = *reinterpret_cast<const float4*>(&bsrc[oc0]);
        *reinterpret_cast<float4*>(&bias[4]) = *reinterpret_cast<const float4*>(&bsrc[oc0 + 4]);
    }
    if (isK) {
        #pragma unroll
        for (int r = 0; r < 8; r++) {
            __half2 hh[4];
            #pragma unroll
            for (int c = 0; c < 4; c++) {
                F2U u; u.u = acc[r][c];
                float2 f = u.f;
                f.x += bias[2 * c]; f.y += bias[2 * c + 1];
                hh[c] = __floats2half2_rn(f.x, f.y);
            }
            *reinterpret_cast<uint4*>(&g_K[((size_t)b * SS + row0 + r) * DD + oc0]) =
                *reinterpret_cast<uint4*>(hh);
        }
    } else {
        float av[8], sv[8];
        *reinterpret_cast<float4*>(&av[0]) = *reinterpret_cast<const float4*>(&g_a[b * DD + oc0]);
        *reinterpret_cast<float4*>(&av[4]) = *reinterpret_cast<const float4*>(&g_a[b * DD + oc0 + 4]);
        *reinterpret_cast<float4*>(&sv[0]) = *reinterpret_cast<const float4*>(&g_s2[b * DD + oc0]);
        *reinterpret_cast<float4*>(&sv[4]) = *reinterpret_cast<const float4*>(&g_s2[b * DD + oc0 + 4]);
        #pragma unroll
        for (int r = 0; r < 8; r++) {
            __half2 hh[4];
            #pragma unroll
            for (int c = 0; c < 4; c++) {
                F2U u; u.u = acc[r][c];
                float2 f = u.f;
                f.x = (f.x + bias[2 * c])     * av[2 * c]     + sv[2 * c];
                f.y = (f.y + bias[2 * c + 1]) * av[2 * c + 1] + sv[2 * c + 1];
                hh[c] = __floats2half2_rn(f.x, f.y);
            }
            *reinterpret_cast<uint4*>(&g_V[((size_t)b * SS + row0 + r) * DD + oc0]) =
                *reinterpret_cast<uint4*>(hh);
        }
    }
}

// =====================================================================
// Kernel 3: attention (2 query rows/batch) + output projection.
//   grid 1024 blocks (one per batch) x 256 threads (8 warps = 8 heads).
// =====================================================================
struct AttnSmem {
    float xr[2][DD];        // the two live X rows (s = 63, 127)
    float qs[2][DD];        // Q for those rows
    float attn[16][SS];     // softmax probs, p = h*2 + qi
    float ao[2][DD];        // attention output (pre O-proj)
    float ebv[NHH];
    float hsv[NHH];
    __half Ksh[SS][260];    // K tile, 4-half row pad (2-way-conflict reads)
};

__global__ void __launch_bounds__(256)
attn_kernel(const float* __restrict__ X,
            const float* __restrict__ Wq, const float* __restrict__ bq,
            const float* __restrict__ Wo, const float* __restrict__ bo,
            float* __restrict__ out)
{
    extern __shared__ char smem_raw[];
    AttnSmem& S = *reinterpret_cast<AttnSmem*>(smem_raw);
    const int b = blockIdx.x;
    const int t = threadIdx.x;

    // ---- stage K tile (fp16, 64 KB) ----
    const uint2* Ksrc = reinterpret_cast<const uint2*>(g_K + (size_t)b * SS * DD);
    #pragma unroll
    for (int i = 0; i < 32; i++) {
        int s = t + i * 256;            // 0..8191
        int row = s >> 6, c4 = s & 63;  // 64 uint2 per row
        *reinterpret_cast<uint2*>(&S.Ksh[row][c4 * 4]) = Ksrc[row * 64 + c4];
    }
    S.xr[0][t] = X[((size_t)b * SS + 63) * DD + t];
    S.xr[1][t] = X[((size_t)b * SS + 127) * DD + t];
    if (t < NHH)            S.ebv[t]       = g_eb[b * NHH + t];
    else if (t < 2 * NHH)   S.hsv[t - NHH] = g_hs[b * NHH + (t - NHH)];
    __syncthreads();

    // ---- Q projection for the 2 rows ----
    #pragma unroll
    for (int qi = 0; qi < 2; qi++) {
        float acc = bq[t];
        #pragma unroll 4
        for (int k = 0; k < DD; k++) acc += S.xr[qi][k] * Wq[k * DD + t];
        S.qs[qi][t] = acc;
    }
    __syncthreads();

    // ---- scores + softmax: warp w handles head w, both query rows ----
    const int w = t >> 5, l = t & 31;
    #pragma unroll
    for (int qi = 0; qi < 2; qi++) {
        float sv[4];
        const int kb = qi ? 63 : 127;   // the one biased key
        #pragma unroll
        for (int j = 0; j < 4; j++) {
            const int k = l + 32 * j;
            const __half* kr = &S.Ksh[k][w * HDD];
            const float*  qp = &S.qs[qi][w * HDD];
            float acc = 0.0f;
            #pragma unroll
            for (int d2 = 0; d2 < 16; d2++) {
                float2 kv = __half22float2(*reinterpret_cast<const __half2*>(kr + 2 * d2));
                acc += qp[2 * d2] * kv.x + qp[2 * d2 + 1] * kv.y;
            }
            float s = acc * S.hsv[w];
            if (k == kb) s += S.ebv[w];
            sv[j] = s;
        }
        float m = fmaxf(fmaxf(sv[0], sv[1]), fmaxf(sv[2], sv[3]));
        #pragma unroll
        for (int o = 16; o > 0; o >>= 1) m = fmaxf(m, __shfl_xor_sync(0xffffffffu, m, o));
        float e[4], sum = 0.0f;
        #pragma unroll
        for (int j = 0; j < 4; j++) { e[j] = expf(sv[j] - m); sum += e[j]; }
        #pragma unroll
        for (int o = 16; o > 0; o >>= 1) sum += __shfl_xor_sync(0xffffffffu, sum, o);
        const float inv = 1.0f / sum;
        #pragma unroll
        for (int j = 0; j < 4; j++) S.attn[w * 2 + qi][l + 32 * j] = e[j] * inv;
    }
    __syncthreads();

    // ---- attn @ V ----
    const __half* Vb = g_V + (size_t)b * SS * DD;
    #pragma unroll
    for (int oi = 0; oi < 2; oi++) {
        const int idx = t + oi * 256;
        const int p = idx >> 5, d = idx & 31;
        const int h = p >> 1, qi = p & 1;
        float acc = 0.0f;
        #pragma unroll 4
        for (int k = 0; k < SS; k++)
            acc += S.attn[p][k] * __half2float(Vb[k * DD + h * HDD + d]);
        S.ao[qi][h * HDD + d] = acc;
    }
    __syncthreads();

    // ---- output projection ----
    #pragma unroll
    for (int qi = 0; qi < 2; qi++) {
        float acc = bo[t];
        #pragma unroll 4
        for (int c = 0; c < DD; c++) acc += S.ao[qi][c] * Wo[c * DD + t];
        out[((size_t)b * 2 + qi) * DD + t] = acc;
    }
}

// =====================================================================
extern "C" void kernel_launch(void* const* d_in, const int* in_sizes, int n_in,
                              void* d_out, int out_size)
{
    (void)in_sizes; (void)n_in; (void)out_size;
    const float* X      = (const float*)d_in[0];
    const float* EF     = (const float*)d_in[1];
    const float* Wq     = (const float*)d_in[2];
    const float* bq     = (const float*)d_in[3];
    const float* Wk     = (const float*)d_in[4];
    const float* bk     = (const float*)d_in[5];
    const float* Wv     = (const float*)d_in[6];
    const float* bv     = (const float*)d_in[7];
    const float* Wo     = (const float*)d_in[8];
    const float* bo     = (const float*)d_in[9];
    const float* Wbias  = (const float*)d_in[10];
    const float* bbias  = (const float*)d_in[11];
    const float* Wgate  = (const float*)d_in[12];
    const float* bgate  = (const float*)d_in[13];
    const float* Wscale = (const float*)d_in[14];
    const float* bscale = (const float*)d_in[15];
    const float* Wshift = (const float*)d_in[16];
    const float* bshift = (const float*)d_in[17];
    const float* Whead  = (const float*)d_in[18];
    const float* bhead  = (const float*)d_in[19];
    float* out = (float*)d_out;

    cudaFuncSetAttribute(attn_kernel, cudaFuncAttributeMaxDynamicSharedMemorySize,
                         (int)sizeof(AttnSmem));

    edge_kernel<<<128, 256>>>(EF, Wgate, bgate, Wscale, bscale,
                              Wshift, bshift, Wbias, bbias, Whead, bhead);
    gemm_kv_kernel<<<dim3(4, 1024), 256>>>(X, Wk, bk, Wv, bv);
    attn_kernel<<<1024, 256, sizeof(AttnSmem)>>>(X, Wq, bq, Wo, bo, out);
}

// round 3
// speedup vs baseline: 1.0066x; 1.0066x over previous
#include <cuda_runtime.h>
#include <cuda_fp16.h>
#include <math.h>

// Problem constants
#define BB 1024
#define SS 128      // N*HIST
#define DD 256
#define EE 128
#define NHH 8
#define HDD 32
#define INV_SQRT_HD 0.17677669529663687f

// ---------------- device scratch (allowed: __device__ globals) ----------------
__device__ __align__(16) __half g_K[(size_t)BB * SS * DD];   // 64 MB
__device__ __align__(16) __half g_V[(size_t)BB * SS * DD];   // 64 MB
__device__ __align__(16) float  g_a [BB * DD];               // gate*(1+tanh(scale))
__device__ __align__(16) float  g_s2[BB * DD];               // gate*shift
__device__ __align__(16) float  g_eb[BB * NHH];
__device__ __align__(16) float  g_hs[BB * NHH];              // (1+tanh(head))*inv_sqrt(HD)

// ---------------- f32x2 helpers ----------------
__device__ __forceinline__ unsigned long long splat2(float x) {
    unsigned long long r;
    asm("mov.b64 %0, {%1, %1};" : "=l"(r) : "f"(x));
    return r;
}
__device__ __forceinline__ void ffma2(unsigned long long& a,
                                      unsigned long long x,
                                      unsigned long long w) {
    asm("fma.rn.f32x2 %0, %1, %2, %0;" : "+l"(a) : "l"(x), "l"(w));
}
union F2U { unsigned long long u; float2 f; };

// =====================================================================
// Kernel 1: edge MLPs.  grid 128 blocks x 256 threads, 8 batches/block.
// =====================================================================
__global__ void __launch_bounds__(256)
edge_kernel(const float* __restrict__ EF,
            const float* __restrict__ Wgate, const float* __restrict__ bgate,
            const float* __restrict__ Wscale, const float* __restrict__ bscale,
            const float* __restrict__ Wshift, const float* __restrict__ bshift,
            const float* __restrict__ Wbias, const float* __restrict__ bbias,
            const float* __restrict__ Whead, const float* __restrict__ bhead)
{
    __shared__ float ef[8][EE];
    const int b0 = blockIdx.x * 8;
    const int t  = threadIdx.x;

    #pragma unroll
    for (int i = 0; i < 4; i++) {
        int s  = t + i * 256;        // 0..1023
        int bi = s >> 7, e = s & 127;
        ef[bi][e] = EF[(size_t)(b0 + bi) * EE + e];
    }
    __syncthreads();

    // gate / scale / shift for all 8 batches, channel c = t
    {
        const int c = t;
        float ag[8], as[8], ah[8];
        const float bg = bgate[c], bs = bscale[c], bh = bshift[c];
        #pragma unroll
        for (int i = 0; i < 8; i++) { ag[i] = bg; as[i] = bs; ah[i] = bh; }
        for (int e = 0; e < EE; e++) {
            const float wg = Wgate[e * DD + c];
            const float ws = Wscale[e * DD + c];
            const float wh = Wshift[e * DD + c];
            #pragma unroll
            for (int i = 0; i < 8; i++) {
                const float f = ef[i][e];
                ag[i] += f * wg; as[i] += f * ws; ah[i] += f * wh;
            }
        }
        #pragma unroll
        for (int i = 0; i < 8; i++) {
            const float gate = 1.0f / (1.0f + expf(-ag[i]));
            const float sc   = tanhf(as[i]);
            g_a [(b0 + i) * DD + c] = gate * (1.0f + sc);
            g_s2[(b0 + i) * DD + c] = gate * ah[i];
        }
    }

    // edge_bias and head_scale (8 heads x 8 batches each)
    if (t < 64) {
        const int bi = t >> 3, h = t & 7;
        float acc = bbias[h];
        for (int e = 0; e < EE; e++) acc += ef[bi][e] * Wbias[e * NHH + h];
        g_eb[(b0 + bi) * NHH + h] = acc;
    } else if (t < 128) {
        const int u = t - 64;
        const int bi = u >> 3, h = u & 7;
        float acc = bhead[h];
        for (int e = 0; e < EE; e++) acc += ef[bi][e] * Whead[e * NHH + h];
        g_hs[(b0 + bi) * NHH + h] = (1.0f + tanhf(acc)) * INV_SQRT_HD;
    }
}

// =====================================================================
// Kernel 2: K/V projection GEMM.
//   grid (4, 1024): blockIdx.y = batch (128 rows), blockIdx.x = 128-col tile
//   of the 512-wide concat [Wk | Wv].  256 threads, 8x8 micro-tiles, f32x2.
//   Epilogue: +bias, V gating, fp16 store.
// =====================================================================
__global__ void __launch_bounds__(256, 2)
gemm_kv_kernel(const float* __restrict__ X,
               const float* __restrict__ Wk, const float* __restrict__ bk,
               const float* __restrict__ Wv, const float* __restrict__ bv)
{
    const int b  = blockIdx.y;
    const int nb = blockIdx.x;            // 0,1 -> K ; 2,3 -> V
    const bool isK = (nb < 2);
    const int colbase = (nb & 1) * 128;   // within the 256-wide W
    const float* __restrict__ W = isK ? Wk : Wv;

    __shared__ __align__(16) float Xs[2][16][128];
    __shared__ __align__(16) float Ws[2][16][128];

    const int t  = threadIdx.x;
    const int tx = t & 15, ty = t >> 4;

    const float4* X4 = reinterpret_cast<const float4*>(X + (size_t)b * SS * DD);

    unsigned long long acc[8][4];
    #pragma unroll
    for (int r = 0; r < 8; r++)
        #pragma unroll
        for (int c = 0; c < 4; c++) acc[r][c] = 0ull;

    float4 rx[2], rw[2];

    // ---- load chunk 0 ----
    #pragma unroll
    for (int i = 0; i < 2; i++) {
        int s = t + i * 256;
        int kq = s & 3, row = s >> 2;
        rx[i] = X4[row * 64 + 0 + kq];
        int col4 = s & 31, kk = s >> 5;
        rw[i] = reinterpret_cast<const float4*>(W + (size_t)kk * DD + colbase)[col4];
    }
    #pragma unroll
    for (int i = 0; i < 2; i++) {
        int s = t + i * 256;
        int kq = s & 3, row = s >> 2;
        Xs[0][kq * 4 + 0][row] = rx[i].x;
        Xs[0][kq * 4 + 1][row] = rx[i].y;
        Xs[0][kq * 4 + 2][row] = rx[i].z;
        Xs[0][kq * 4 + 3][row] = rx[i].w;
        int col4 = s & 31, kk = s >> 5;
        *reinterpret_cast<float4*>(&Ws[0][kk][col4 * 4]) = rw[i];
    }
    __syncthreads();

    for (int ch = 0; ch < 16; ch++) {
        const int cur = ch & 1;
        if (ch < 15) {
            const int k0q = (ch + 1) * 4;
            const int k0  = (ch + 1) * 16;
            #pragma unroll
            for (int i = 0; i < 2; i++) {
                int s = t + i * 256;
                int kq = s & 3, row = s >> 2;
                rx[i] = X4[row * 64 + k0q + kq];
                int col4 = s & 31, kk = s >> 5;
                rw[i] = reinterpret_cast<const float4*>(W + (size_t)(k0 + kk) * DD + colbase)[col4];
            }
        }
        #pragma unroll
        for (int kk = 0; kk < 16; kk++) {
            const float4 xa = *reinterpret_cast<const float4*>(&Xs[cur][kk][ty * 8]);
            const float4 xb = *reinterpret_cast<const float4*>(&Xs[cur][kk][ty * 8 + 4]);
            unsigned long long wp[4];
            #pragma unroll
            for (int c = 0; c < 4; c++)
                wp[c] = *reinterpret_cast<const unsigned long long*>(&Ws[cur][kk][tx * 8 + 2 * c]);
            unsigned long long xs[8];
            xs[0] = splat2(xa.x); xs[1] = splat2(xa.y); xs[2] = splat2(xa.z); xs[3] = splat2(xa.w);
            xs[4] = splat2(xb.x); xs[5] = splat2(xb.y); xs[6] = splat2(xb.z); xs[7] = splat2(xb.w);
            #pragma unroll
            for (int r = 0; r < 8; r++)
                #pragma unroll
                for (int c = 0; c < 4; c++)
                    ffma2(acc[r][c], xs[r], wp[c]);
        }
        if (ch < 15) {
            const int nxt = cur ^ 1;
            #pragma unroll
            for (int i = 0; i < 2; i++) {
                int s = t + i * 256;
                int kq = s & 3, row = s >> 2;
                Xs[nxt][kq * 4 + 0][row] = rx[i].x;
                Xs[nxt][kq * 4 + 1][row] = rx[i].y;
                Xs[nxt][kq * 4 + 2][row] = rx[i].z;
                Xs[nxt][kq * 4 + 3][row] = rx[i].w;
                int col4 = s & 31, kk = s >> 5;
                *reinterpret_cast<float4*>(&Ws[nxt][kk][col4 * 4]) = rw[i];
            }
            __syncthreads();
        }
    }

    // ---- epilogue ----
    const int row0 = ty * 8;
    const int oc0  = colbase + tx * 8;      // column within 0..255 of K or V
    float bias[8];
    {
        const float* bsrc = isK ? bk : bv;
        *reinterpret_cast<float4*>(&bias[0]) = *reinterpret_cast<const float4*>(&bsrc[oc0]);
        *reinterpret_cast<float4*>(&bias[4]) = *reinterpret_cast<const float4*>(&bsrc[oc0 + 4]);
    }
    if (isK) {
        #pragma unroll
        for (int r = 0; r < 8; r++) {
            __half2 hh[4];
            #pragma unroll
            for (int c = 0; c < 4; c++) {
                F2U u; u.u = acc[r][c];
                float2 f = u.f;
                f.x += bias[2 * c]; f.y += bias[2 * c + 1];
                hh[c] = __floats2half2_rn(f.x, f.y);
            }
            *reinterpret_cast<uint4*>(&g_K[((size_t)b * SS + row0 + r) * DD + oc0]) =
                *reinterpret_cast<uint4*>(hh);
        }
    } else {
        float av[8], sv[8];
        *reinterpret_cast<float4*>(&av[0]) = *reinterpret_cast<const float4*>(&g_a[b * DD + oc0]);
        *reinterpret_cast<float4*>(&av[4]) = *reinterpret_cast<const float4*>(&g_a[b * DD + oc0 + 4]);
        *reinterpret_cast<float4*>(&sv[0]) = *reinterpret_cast<const float4*>(&g_s2[b * DD + oc0]);
        *reinterpret_cast<float4*>(&sv[4]) = *reinterpret_cast<const float4*>(&g_s2[b * DD + oc0 + 4]);
        #pragma unroll
        for (int r = 0; r < 8; r++) {
            __half2 hh[4];
            #pragma unroll
            for (int c = 0; c < 4; c++) {
                F2U u; u.u = acc[r][c];
                float2 f = u.f;
                f.x = (f.x + bias[2 * c])     * av[2 * c]     + sv[2 * c];
                f.y = (f.y + bias[2 * c + 1]) * av[2 * c + 1] + sv[2 * c + 1];
                hh[c] = __floats2half2_rn(f.x, f.y);
            }
            *reinterpret_cast<uint4*>(&g_V[((size_t)b * SS + row0 + r) * DD + oc0]) =
                *reinterpret_cast<uint4*>(hh);
        }
    }
}

// =====================================================================
// Kernel 3: attention (2 query rows/batch) + output projection.
//   grid 1024 blocks (one per batch) x 256 threads (8 warps = 8 heads).
// =====================================================================
struct AttnSmem {
    float xr[2][DD];        // the two live X rows (s = 63, 127)
    float qs[2][DD];        // Q for those rows
    float attn[16][SS];     // softmax probs, p = h*2 + qi
    float ao[2][DD];        // attention output (pre O-proj)
    float ebv[NHH];
    float hsv[NHH];
    __half Ksh[SS][260];    // K tile, 4-half row pad (2-way-conflict reads)
};

__global__ void __launch_bounds__(256)
attn_kernel(const float* __restrict__ X,
            const float* __restrict__ Wq, const float* __restrict__ bq,
            const float* __restrict__ Wo, const float* __restrict__ bo,
            float* __restrict__ out)
{
    extern __shared__ char smem_raw[];
    AttnSmem& S = *reinterpret_cast<AttnSmem*>(smem_raw);
    const int b = blockIdx.x;
    const int t = threadIdx.x;

    // ---- stage K tile (fp16, 64 KB) ----
    const uint2* Ksrc = reinterpret_cast<const uint2*>(g_K + (size_t)b * SS * DD);
    #pragma unroll
    for (int i = 0; i < 32; i++) {
        int s = t + i * 256;            // 0..8191
        int row = s >> 6, c4 = s & 63;  // 64 uint2 per row
        *reinterpret_cast<uint2*>(&S.Ksh[row][c4 * 4]) = Ksrc[row * 64 + c4];
    }
    S.xr[0][t] = X[((size_t)b * SS + 63) * DD + t];
    S.xr[1][t] = X[((size_t)b * SS + 127) * DD + t];
    if (t < NHH)            S.ebv[t]       = g_eb[b * NHH + t];
    else if (t < 2 * NHH)   S.hsv[t - NHH] = g_hs[b * NHH + (t - NHH)];
    __syncthreads();

    // ---- Q projection for the 2 rows ----
    #pragma unroll
    for (int qi = 0; qi < 2; qi++) {
        float acc = bq[t];
        #pragma unroll 4
        for (int k = 0; k < DD; k++) acc += S.xr[qi][k] * Wq[k * DD + t];
        S.qs[qi][t] = acc;
    }
    __syncthreads();

    // ---- scores + softmax: warp w handles head w, both query rows ----
    const int w = t >> 5, l = t & 31;
    #pragma unroll
    for (int qi = 0; qi < 2; qi++) {
        float sv[4];
        const int kb = qi ? 63 : 127;   // the one biased key
        #pragma unroll
        for (int j = 0; j < 4; j++) {
            const int k = l + 32 * j;
            const __half* kr = &S.Ksh[k][w * HDD];
            const float*  qp = &S.qs[qi][w * HDD];
            float acc = 0.0f;
            #pragma unroll
            for (int d2 = 0; d2 < 16; d2++) {
                float2 kv = __half22float2(*reinterpret_cast<const __half2*>(kr + 2 * d2));
                acc += qp[2 * d2] * kv.x + qp[2 * d2 + 1] * kv.y;
            }
            float s = acc * S.hsv[w];
            if (k == kb) s += S.ebv[w];
            sv[j] = s;
        }
        float m = fmaxf(fmaxf(sv[0], sv[1]), fmaxf(sv[2], sv[3]));
        #pragma unroll
        for (int o = 16; o > 0; o >>= 1) m = fmaxf(m, __shfl_xor_sync(0xffffffffu, m, o));
        float e[4], sum = 0.0f;
        #pragma unroll
        for (int j = 0; j < 4; j++) { e[j] = expf(sv[j] - m); sum += e[j]; }
        #pragma unroll
        for (int o = 16; o > 0; o >>= 1) sum += __shfl_xor_sync(0xffffffffu, sum, o);
        const float inv = 1.0f / sum;
        #pragma unroll
        for (int j = 0; j < 4; j++) S.attn[w * 2 + qi][l + 32 * j] = e[j] * inv;
    }
    __syncthreads();

    // ---- attn @ V ----
    const __half* Vb = g_V + (size_t)b * SS * DD;
    #pragma unroll
    for (int oi = 0; oi < 2; oi++) {
        const int idx = t + oi * 256;
        const int p = idx >> 5, d = idx & 31;
        const int h = p >> 1, qi = p & 1;
        float acc = 0.0f;
        #pragma unroll 4
        for (int k = 0; k < SS; k++)
            acc += S.attn[p][k] * __half2float(Vb[k * DD + h * HDD + d]);
        S.ao[qi][h * HDD + d] = acc;
    }
    __syncthreads();

    // ---- output projection ----
    #pragma unroll
    for (int qi = 0; qi < 2; qi++) {
        float acc = bo[t];
        #pragma unroll 4
        for (int c = 0; c < DD; c++) acc += S.ao[qi][c] * Wo[c * DD + t];
        out[((size_t)b * 2 + qi) * DD + t] = acc;
    }
}

// =====================================================================
extern "C" void kernel_launch(void* const* d_in, const int* in_sizes, int n_in,
                              void* d_out, int out_size)
{
    (void)in_sizes; (void)n_in; (void)out_size;
    const float* X      = (const float*)d_in[0];
    const float* EF     = (const float*)d_in[1];
    const float* Wq     = (const float*)d_in[2];
    const float* bq     = (const float*)d_in[3];
    const float* Wk     = (const float*)d_in[4];
    const float* bk     = (const float*)d_in[5];
    const float* Wv     = (const float*)d_in[6];
    const float* bv     = (const float*)d_in[7];
    const float* Wo     = (const float*)d_in[8];
    const float* bo     = (const float*)d_in[9];
    const float* Wbias  = (const float*)d_in[10];
    const float* bbias  = (const float*)d_in[11];
    const float* Wgate  = (const float*)d_in[12];
    const float* bgate  = (const float*)d_in[13];
    const float* Wscale = (const float*)d_in[14];
    const float* bscale = (const float*)d_in[15];
    const float* Wshift = (const float*)d_in[16];
    const float* bshift = (const float*)d_in[17];
    const float* Whead  = (const float*)d_in[18];
    const float* bhead  = (const float*)d_in[19];
    float* out = (float*)d_out;

    cudaFuncSetAttribute(attn_kernel, cudaFuncAttributeMaxDynamicSharedMemorySize,
                         (int)sizeof(AttnSmem));

    edge_kernel<<<128, 256>>>(EF, Wgate, bgate, Wscale, bscale,
                              Wshift, bshift, Wbias, bbias, Whead, bhead);
    gemm_kv_kernel<<<dim3(4, 1024), 256>>>(X, Wk, bk, Wv, bv);
    attn_kernel<<<1024, 256, sizeof(AttnSmem)>>>(X, Wq, bq, Wo, bo, out);
}

// round 5
// speedup vs baseline: 5.1212x; 5.0875x over previous
#include <cuda_runtime.h>
#include <cuda_fp16.h>
#include <math.h>

#define BB 1024
#define SS 128
#define DD 256
#define EE 128
#define NHH 8
#define HDD 32
#define INV_SQRT_HD 0.17677669529663687f
#define RSH 264                 // smem tile row pitch in halves
#define RSB (RSH * 2)           // 528 bytes

// ---------------- device scratch ----------------
__device__ __align__(16) __half g_K [(size_t)BB * SS * DD];
__device__ __align__(16) __half g_V [(size_t)BB * SS * DD];
__device__ __align__(16) __half g_Wt[1024 * 256];   // [WkT|WvT|WqT|WoT] fp16 [n][k]
__device__ __align__(16) __half g_Xq[2 * BB * DD];  // gathered q-input rows fp16
__device__ __align__(16) __half g_AO[2 * BB * DD];  // attention out fp16
__device__ __align__(16) float  g_Q [2 * BB * DD];  // projected Q fp32
__device__ __align__(16) float  g_a [BB * DD];
__device__ __align__(16) float  g_s2[BB * DD];
__device__ __align__(16) float  g_eb[BB * NHH];
__device__ __align__(16) float  g_hs[BB * NHH];

// ---------------- helpers ----------------
__device__ __forceinline__ unsigned smem_u32(const void* p) {
    unsigned a;
    asm("{ .reg .u64 t; cvta.to.shared.u64 t, %1; cvt.u32.u64 %0, t; }" : "=r"(a) : "l"(p));
    return a;
}
__device__ __forceinline__ void ldsm4(unsigned& r0, unsigned& r1, unsigned& r2, unsigned& r3,
                                      unsigned a) {
    asm volatile("ldmatrix.sync.aligned.m8n8.x4.shared.b16 {%0,%1,%2,%3}, [%4];"
                 : "=r"(r0), "=r"(r1), "=r"(r2), "=r"(r3) : "r"(a));
}
__device__ __forceinline__ void mma16816(float c[4], const unsigned a[4],
                                         unsigned b0, unsigned b1) {
    asm volatile("mma.sync.aligned.m16n8k16.row.col.f32.f16.f16.f32 "
        "{%0,%1,%2,%3}, {%4,%5,%6,%7}, {%8,%9}, {%0,%1,%2,%3};"
        : "+f"(c[0]), "+f"(c[1]), "+f"(c[2]), "+f"(c[3])
        : "r"(a[0]), "r"(a[1]), "r"(a[2]), "r"(a[3]), "r"(b0), "r"(b1));
}

// Warp computes a 32x64 tile: acc[mt][nt][4], K=256 (16 k-steps).
// Abase/Bbase = smem byte addrs of this warp's first row.
__device__ __forceinline__ void warp_gemm(float acc[2][8][4], unsigned Abase,
                                          unsigned Bbase, int lane) {
    unsigned aAddr0 = Abase + (unsigned)(lane & 15) * RSB + (unsigned)(lane >> 4) * 16u;
    unsigned aAddr1 = aAddr0 + 16u * RSB;
    unsigned bAddr  = Bbase + (unsigned)((lane & 7) + ((lane >> 4) << 3)) * RSB
                            + (unsigned)((lane >> 3) & 1) * 16u;
    #pragma unroll
    for (int ks = 0; ks < 16; ks++) {
        const unsigned ko = (unsigned)ks * 32u;
        unsigned a0[4], a1[4], bb[4][4];
        ldsm4(a0[0], a0[1], a0[2], a0[3], aAddr0 + ko);
        ldsm4(a1[0], a1[1], a1[2], a1[3], aAddr1 + ko);
        #pragma unroll
        for (int g = 0; g < 4; g++)
            ldsm4(bb[g][0], bb[g][1], bb[g][2], bb[g][3], bAddr + g * (16u * RSB) + ko);
        #pragma unroll
        for (int g = 0; g < 4; g++) {
            mma16816(acc[0][2 * g + 0], a0, bb[g][0], bb[g][1]);
            mma16816(acc[0][2 * g + 1], a0, bb[g][2], bb[g][3]);
            mma16816(acc[1][2 * g + 0], a1, bb[g][0], bb[g][1]);
            mma16816(acc[1][2 * g + 1], a1, bb[g][2], bb[g][3]);
        }
    }
}

// =====================================================================
// prep: transpose+convert Wk|Wv|Wq|Wo -> g_Wt fp16 [1024 n][256 k]
// =====================================================================
__global__ void __launch_bounds__(256)
convert_w_kernel(const float* __restrict__ Wk, const float* __restrict__ Wv,
                 const float* __restrict__ Wq, const float* __restrict__ Wo)
{
    __shared__ float tile[32][33];
    const int n0 = blockIdx.x * 32, k0 = blockIdx.y * 32;
    const float* W = (n0 < 256) ? Wk : (n0 < 512) ? Wv : (n0 < 768) ? Wq : Wo;
    const int ncol = n0 & 255;
    #pragma unroll
    for (int i = 0; i < 4; i++) {
        int k = k0 + threadIdx.y + i * 8;
        tile[threadIdx.y + i * 8][threadIdx.x] = W[k * 256 + ncol + threadIdx.x];
    }
    __syncthreads();
    #pragma unroll
    for (int i = 0; i < 4; i++) {
        int n = n0 + threadIdx.y + i * 8;
        g_Wt[(size_t)n * 256 + k0 + threadIdx.x] =
            __float2half(tile[threadIdx.x][threadIdx.y + i * 8]);
    }
}

// prep: gather X rows 63/127 per batch -> g_Xq fp16 [2048][256]
__global__ void __launch_bounds__(256)
gather_xq_kernel(const float* __restrict__ X)
{
    int i = blockIdx.x * 256 + threadIdx.x;     // 262144 half2 slots
    int row = i >> 7, cp = i & 127;
    int b = row >> 1, s = (row & 1) ? 127 : 63;
    float2 v = reinterpret_cast<const float2*>(X)[(((size_t)b * SS + s) * DD >> 1) + cp];
    reinterpret_cast<__half2*>(g_Xq)[i] = __floats2half2_rn(v.x, v.y);
}

// =====================================================================
// edge MLPs (2 batches/block, 512 blocks)
// =====================================================================
__global__ void __launch_bounds__(256)
edge_kernel(const float* __restrict__ EF,
            const float* __restrict__ Wgate, const float* __restrict__ bgate,
            const float* __restrict__ Wscale, const float* __restrict__ bscale,
            const float* __restrict__ Wshift, const float* __restrict__ bshift,
            const float* __restrict__ Wbias, const float* __restrict__ bbias,
            const float* __restrict__ Whead, const float* __restrict__ bhead)
{
    __shared__ float ef[2][EE];
    const int b0 = blockIdx.x * 2;
    const int t = threadIdx.x;
    ef[t >> 7][t & 127] = EF[(size_t)(b0 + (t >> 7)) * EE + (t & 127)];
    __syncthreads();
    {
        const int c = t;
        float ag[2], as[2], ah[2];
        ag[0] = ag[1] = bgate[c];
        as[0] = as[1] = bscale[c];
        ah[0] = ah[1] = bshift[c];
        for (int e = 0; e < EE; e++) {
            const float wg = Wgate[e * DD + c], ws = Wscale[e * DD + c], wh = Wshift[e * DD + c];
            #pragma unroll
            for (int i = 0; i < 2; i++) {
                const float f = ef[i][e];
                ag[i] += f * wg; as[i] += f * ws; ah[i] += f * wh;
            }
        }
        #pragma unroll
        for (int i = 0; i < 2; i++) {
            const float gate = 1.0f / (1.0f + expf(-ag[i]));
            g_a [(b0 + i) * DD + c] = gate * (1.0f + tanhf(as[i]));
            g_s2[(b0 + i) * DD + c] = gate * ah[i];
        }
    }
    if (t < 16) {
        const int bi = t >> 3, h = t & 7;
        float acc = bbias[h];
        for (int e = 0; e < EE; e++) acc += ef[bi][e] * Wbias[e * NHH + h];
        g_eb[(b0 + bi) * NHH + h] = acc;
    } else if (t < 32) {
        const int u = t - 16, bi = u >> 3, h = u & 7;
        float acc = bhead[h];
        for (int e = 0; e < EE; e++) acc += ef[bi][e] * Whead[e * NHH + h];
        g_hs[(b0 + bi) * NHH + h] = (1.0f + tanhf(acc)) * INV_SQRT_HD;
    }
}

// =====================================================================
// KV projection GEMM on mma.sync.  One CTA per batch.
//   smem: sb[1024 f32] | A[128][264] half | B[128][264] half
// =====================================================================
#define KV_SB   0u
#define KV_A    4096u
#define KV_B    (4096u + 128u * RSB)
#define KV_SMEM (4096 + 2 * 128 * RSB)

__global__ void __launch_bounds__(256)
kv_mma_kernel(const float* __restrict__ X,
              const float* __restrict__ bk, const float* __restrict__ bv)
{
    extern __shared__ __align__(16) char sm[];
    const unsigned smb = smem_u32(sm);
    float* sb = reinterpret_cast<float*>(sm);
    const int t = threadIdx.x, w = t >> 5, lane = t & 31;
    const int b = blockIdx.x;
    const int wm = (w & 3) * 32;          // warp row base
    const int wn = (w >> 2) * 64;         // warp col base within 128 pass tile

    sb[t]       = bk[t];
    sb[256 + t] = bv[t];
    sb[512 + t] = g_a [b * DD + t];
    sb[768 + t] = g_s2[b * DD + t];

    // A tile: X_b fp32 -> fp16 smem (row pitch 264)
    const float4* X4 = reinterpret_cast<const float4*>(X) + (size_t)b * SS * 64;
    #pragma unroll
    for (int i = 0; i < 32; i++) {
        int idx = t + i * 256;            // 8192 float4 groups
        int r = idx >> 6, kq = idx & 63;
        float4 v = X4[idx];
        __half2 h0 = __floats2half2_rn(v.x, v.y);
        __half2 h1 = __floats2half2_rn(v.z, v.w);
        uint2 pk;
        pk.x = *reinterpret_cast<unsigned*>(&h0);
        pk.y = *reinterpret_cast<unsigned*>(&h1);
        *reinterpret_cast<uint2*>(sm + KV_A + (size_t)r * RSB + kq * 8) = pk;
    }

    const unsigned Abase = smb + KV_A + (unsigned)wm * RSB;
    const unsigned Bbase = smb + KV_B + (unsigned)wn * RSB;

    for (int p = 0; p < 4; p++) {
        // load B pass tile: g_Wt rows [p*128, p*128+128)
        const uint4* src = reinterpret_cast<const uint4*>(g_Wt) + (size_t)p * 128 * 32;
        #pragma unroll
        for (int i = 0; i < 16; i++) {
            int idx = t + i * 256;        // 4096 uint4
            int r = idx >> 5, c = idx & 31;
            *reinterpret_cast<uint4*>(sm + KV_B + (size_t)r * RSB + c * 16) = src[idx];
        }
        __syncthreads();

        float acc[2][8][4];
        #pragma unroll
        for (int mt = 0; mt < 2; mt++)
            #pragma unroll
            for (int nt = 0; nt < 8; nt++)
                #pragma unroll
                for (int e = 0; e < 4; e++) acc[mt][nt][e] = 0.0f;

        warp_gemm(acc, Abase, Bbase, lane);

        // epilogue
        const bool isK = (p < 2);
        __half* gout = isK ? g_K : g_V;
        #pragma unroll
        for (int mt = 0; mt < 2; mt++) {
            #pragma unroll
            for (int nt = 0; nt < 8; nt++) {
                const int col = ((p * 128 + wn + nt * 8 + (lane & 3) * 2) & 255);
                const int r0 = wm + mt * 16 + (lane >> 2);
                float f0, f1, f2, f3;
                if (isK) {
                    f0 = acc[mt][nt][0] + sb[col];
                    f1 = acc[mt][nt][1] + sb[col + 1];
                    f2 = acc[mt][nt][2] + sb[col];
                    f3 = acc[mt][nt][3] + sb[col + 1];
                } else {
                    const float b0 = sb[256 + col], b1 = sb[256 + col + 1];
                    const float a0 = sb[512 + col], a1 = sb[512 + col + 1];
                    const float s0 = sb[768 + col], s1 = sb[768 + col + 1];
                    f0 = (acc[mt][nt][0] + b0) * a0 + s0;
                    f1 = (acc[mt][nt][1] + b1) * a1 + s1;
                    f2 = (acc[mt][nt][2] + b0) * a0 + s0;
                    f3 = (acc[mt][nt][3] + b1) * a1 + s1;
                }
                *reinterpret_cast<__half2*>(&gout[((size_t)b * SS + r0) * DD + col]) =
                    __floats2half2_rn(f0, f1);
                *reinterpret_cast<__half2*>(&gout[((size_t)b * SS + r0 + 8) * DD + col]) =
                    __floats2half2_rn(f2, f3);
            }
        }
        __syncthreads();
    }
}

// =====================================================================
// Plain GEMM (mma.sync): out[2048][256] f32 = A(fp16) @ Wt-slice + bias
//   mode 0: A=g_Xq, B=WqT (g_Wt+512*256), out=g_Q
//   mode 1: A=g_AO, B=WoT (g_Wt+768*256), out=out_param
// =====================================================================
#define PG_A    0u
#define PG_B    (128u * RSB)
#define PG_SMEM (2 * 128 * RSB)

__global__ void __launch_bounds__(256)
gemm_mma_kernel(int mode, const float* __restrict__ bias, float* __restrict__ out_param)
{
    extern __shared__ __align__(16) char sm[];
    const unsigned smb = smem_u32(sm);
    const int t = threadIdx.x, w = t >> 5, lane = t & 31;
    const int m0 = blockIdx.x * 128;
    const int wm = (w & 3) * 32, wn = (w >> 2) * 64;
    const __half* Ag = mode ? g_AO : g_Xq;
    const __half* Bg = g_Wt + (size_t)(mode ? 768 : 512) * 256;
    float* out = mode ? out_param : g_Q;

    // load A rows m0..m0+127
    const uint4* As = reinterpret_cast<const uint4*>(Ag) + (size_t)m0 * 32;
    #pragma unroll
    for (int i = 0; i < 16; i++) {
        int idx = t + i * 256;
        int r = idx >> 5, c = idx & 31;
        *reinterpret_cast<uint4*>(sm + PG_A + (size_t)r * RSB + c * 16) = As[idx];
    }
    const unsigned Abase = smb + PG_A + (unsigned)wm * RSB;
    const unsigned Bbase = smb + PG_B + (unsigned)wn * RSB;

    for (int p = 0; p < 2; p++) {
        const uint4* Bs = reinterpret_cast<const uint4*>(Bg) + (size_t)p * 128 * 32;
        #pragma unroll
        for (int i = 0; i < 16; i++) {
            int idx = t + i * 256;
            int r = idx >> 5, c = idx & 31;
            *reinterpret_cast<uint4*>(sm + PG_B + (size_t)r * RSB + c * 16) = Bs[idx];
        }
        __syncthreads();

        float acc[2][8][4];
        #pragma unroll
        for (int mt = 0; mt < 2; mt++)
            #pragma unroll
            for (int nt = 0; nt < 8; nt++)
                #pragma unroll
                for (int e = 0; e < 4; e++) acc[mt][nt][e] = 0.0f;

        warp_gemm(acc, Abase, Bbase, lane);

        #pragma unroll
        for (int mt = 0; mt < 2; mt++) {
            #pragma unroll
            for (int nt = 0; nt < 8; nt++) {
                const int col = p * 128 + wn + nt * 8 + (lane & 3) * 2;
                const int r0 = m0 + wm + mt * 16 + (lane >> 2);
                const float b0 = bias[col], b1 = bias[col + 1];
                float2 v0 = make_float2(acc[mt][nt][0] + b0, acc[mt][nt][1] + b1);
                float2 v1 = make_float2(acc[mt][nt][2] + b0, acc[mt][nt][3] + b1);
                *reinterpret_cast<float2*>(&out[(size_t)r0 * DD + col]) = v0;
                *reinterpret_cast<float2*>(&out[(size_t)(r0 + 8) * DD + col]) = v1;
            }
        }
        __syncthreads();
    }
}

// =====================================================================
// Attention core: scores + softmax + AV.  One block per batch.
// =====================================================================
struct AttnSmem {
    float qs[2][DD];
    float attn[16][SS];
    float ebv[NHH];
    float hsv[NHH];
    __half Ksh[SS][260];
    __half Vsh[SS][260];
};

__global__ void __launch_bounds__(256)
attn_kernel()
{
    extern __shared__ __align__(16) char smem_raw[];
    AttnSmem& S = *reinterpret_cast<AttnSmem*>(smem_raw);
    const int b = blockIdx.x;
    const int t = threadIdx.x;

    const uint2* Ksrc = reinterpret_cast<const uint2*>(g_K + (size_t)b * SS * DD);
    const uint2* Vsrc = reinterpret_cast<const uint2*>(g_V + (size_t)b * SS * DD);
    #pragma unroll
    for (int i = 0; i < 32; i++) {
        int s = t + i * 256;
        int row = s >> 6, c4 = s & 63;
        *reinterpret_cast<uint2*>(&S.Ksh[row][c4 * 4]) = Ksrc[s];
        *reinterpret_cast<uint2*>(&S.Vsh[row][c4 * 4]) = Vsrc[s];
    }
    S.qs[0][t] = g_Q[((size_t)b * 2 + 0) * DD + t];
    S.qs[1][t] = g_Q[((size_t)b * 2 + 1) * DD + t];
    if (t < NHH)          S.ebv[t]       = g_eb[b * NHH + t];
    else if (t < 2 * NHH) S.hsv[t - NHH] = g_hs[b * NHH + (t - NHH)];
    __syncthreads();

    const int w = t >> 5, l = t & 31;
    #pragma unroll
    for (int qi = 0; qi < 2; qi++) {
        float sv[4];
        const int kb = qi ? 63 : 127;
        #pragma unroll
        for (int j = 0; j < 4; j++) {
            const int k = l + 32 * j;
            const __half* kr = &S.Ksh[k][w * HDD];
            const float*  qp = &S.qs[qi][w * HDD];
            float acc = 0.0f;
            #pragma unroll
            for (int d2 = 0; d2 < 16; d2++) {
                float2 kv = __half22float2(*reinterpret_cast<const __half2*>(kr + 2 * d2));
                acc += qp[2 * d2] * kv.x + qp[2 * d2 + 1] * kv.y;
            }
            float s = acc * S.hsv[w];
            if (k == kb) s += S.ebv[w];
            sv[j] = s;
        }
        float m = fmaxf(fmaxf(sv[0], sv[1]), fmaxf(sv[2], sv[3]));
        #pragma unroll
        for (int o = 16; o > 0; o >>= 1) m = fmaxf(m, __shfl_xor_sync(0xffffffffu, m, o));
        float e[4], sum = 0.0f;
        #pragma unroll
        for (int j = 0; j < 4; j++) { e[j] = expf(sv[j] - m); sum += e[j]; }
        #pragma unroll
        for (int o = 16; o > 0; o >>= 1) sum += __shfl_xor_sync(0xffffffffu, sum, o);
        const float inv = 1.0f / sum;
        #pragma unroll
        for (int j = 0; j < 4; j++) S.attn[w * 2 + qi][l + 32 * j] = e[j] * inv;
    }
    __syncthreads();

    // AV: thread = (p, dpair), p = h*2+qi
    const int p = t >> 4, dp = t & 15;
    const int h = p >> 1, qi = p & 1;
    const int col = h * HDD + dp * 2;
    float ax = 0.0f, ay = 0.0f;
    #pragma unroll 4
    for (int k = 0; k < SS; k++) {
        const float a = S.attn[p][k];
        float2 v = __half22float2(*reinterpret_cast<const __half2*>(&S.Vsh[k][col]));
        ax += a * v.x; ay += a * v.y;
    }
    *reinterpret_cast<__half2*>(&g_AO[((size_t)b * 2 + qi) * DD + col]) =
        __floats2half2_rn(ax, ay);
}

// =====================================================================
extern "C" void kernel_launch(void* const* d_in, const int* in_sizes, int n_in,
                              void* d_out, int out_size)
{
    (void)in_sizes; (void)n_in; (void)out_size;
    const float* X      = (const float*)d_in[0];
    const float* EF     = (const float*)d_in[1];
    const float* Wq     = (const float*)d_in[2];
    const float* bq     = (const float*)d_in[3];
    const float* Wk     = (const float*)d_in[4];
    const float* bk     = (const float*)d_in[5];
    const float* Wv     = (const float*)d_in[6];
    const float* bv     = (const float*)d_in[7];
    const float* Wo     = (const float*)d_in[8];
    const float* bo     = (const float*)d_in[9];
    const float* Wbias  = (const float*)d_in[10];
    const float* bbias  = (const float*)d_in[11];
    const float* Wgate  = (const float*)d_in[12];
    const float* bgate  = (const float*)d_in[13];
    const float* Wscale = (const float*)d_in[14];
    const float* bscale = (const float*)d_in[15];
    const float* Wshift = (const float*)d_in[16];
    const float* bshift = (const float*)d_in[17];
    const float* Whead  = (const float*)d_in[18];
    const float* bhead  = (const float*)d_in[19];
    float* out = (float*)d_out;

    cudaFuncSetAttribute(kv_mma_kernel,
                         cudaFuncAttributeMaxDynamicSharedMemorySize, KV_SMEM);
    cudaFuncSetAttribute(gemm_mma_kernel,
                         cudaFuncAttributeMaxDynamicSharedMemorySize, PG_SMEM);
    cudaFuncSetAttribute(attn_kernel,
                         cudaFuncAttributeMaxDynamicSharedMemorySize, (int)sizeof(AttnSmem));

    convert_w_kernel<<<dim3(32, 8), dim3(32, 8)>>>(Wk, Wv, Wq, Wo);
    gather_xq_kernel<<<1024, 256>>>(X);
    edge_kernel<<<512, 256>>>(EF, Wgate, bgate, Wscale, bscale,
                              Wshift, bshift, Wbias, bbias, Whead, bhead);
    kv_mma_kernel<<<1024, 256, KV_SMEM>>>(X, bk, bv);
    gemm_mma_kernel<<<16, 256, PG_SMEM>>>(0, bq, nullptr);
    attn_kernel<<<1024, 256, sizeof(AttnSmem)>>>();
    gemm_mma_kernel<<<16, 256, PG_SMEM>>>(1, bo, out);
}

// round 6
// speedup vs baseline: 6.6928x; 1.3069x over previous
#include <cuda_runtime.h>
#include <cuda_fp16.h>
#include <math.h>

#define BB 1024
#define SS 128
#define DD 256
#define EE 128
#define NHH 8
#define HDD 32
#define INV_SQRT_HD 0.17677669529663687f
#define RSH 264
#define RSB (RSH * 2)           // 528 bytes row pitch

// ---------------- device scratch ----------------
__device__ __align__(16) __half g_Wt[1024 * 256];   // [WkT|WvT|WqT|WoT] fp16 [n][k]
__device__ __align__(16) __half g_Xq[2 * BB * DD];
__device__ __align__(16) __half g_AO[2 * BB * DD];
__device__ __align__(16) float  g_Q [2 * BB * DD];
__device__ __align__(16) float  g_a [BB * DD];
__device__ __align__(16) float  g_s2[BB * DD];
__device__ __align__(16) float  g_eb[BB * NHH];
__device__ __align__(16) float  g_hs[BB * NHH];

// ---------------- helpers ----------------
__device__ __forceinline__ unsigned smem_u32(const void* p) {
    unsigned a;
    asm("{ .reg .u64 t; cvta.to.shared.u64 t, %1; cvt.u32.u64 %0, t; }" : "=r"(a) : "l"(p));
    return a;
}
__device__ __forceinline__ void ldsm4(unsigned& r0, unsigned& r1, unsigned& r2, unsigned& r3,
                                      unsigned a) {
    asm volatile("ldmatrix.sync.aligned.m8n8.x4.shared.b16 {%0,%1,%2,%3}, [%4];"
                 : "=r"(r0), "=r"(r1), "=r"(r2), "=r"(r3) : "r"(a));
}
__device__ __forceinline__ void mma16816(float c[4], const unsigned a[4],
                                         unsigned b0, unsigned b1) {
    asm volatile("mma.sync.aligned.m16n8k16.row.col.f32.f16.f16.f32 "
        "{%0,%1,%2,%3}, {%4,%5,%6,%7}, {%8,%9}, {%0,%1,%2,%3};"
        : "+f"(c[0]), "+f"(c[1]), "+f"(c[2]), "+f"(c[3])
        : "r"(a[0]), "r"(a[1]), "r"(a[2]), "r"(a[3]), "r"(b0), "r"(b1));
}

// Warp computes 32x64 tile, K=256 (16 k-steps).
__device__ __forceinline__ void warp_gemm(float acc[2][8][4], unsigned Abase,
                                          unsigned Bbase, int lane) {
    unsigned aAddr0 = Abase + (unsigned)(lane & 15) * RSB + (unsigned)(lane >> 4) * 16u;
    unsigned aAddr1 = aAddr0 + 16u * RSB;
    unsigned bAddr  = Bbase + (unsigned)((lane & 7) + ((lane >> 4) << 3)) * RSB
                            + (unsigned)((lane >> 3) & 1) * 16u;
    #pragma unroll
    for (int ks = 0; ks < 16; ks++) {
        const unsigned ko = (unsigned)ks * 32u;
        unsigned a0[4], a1[4], bb[4][4];
        ldsm4(a0[0], a0[1], a0[2], a0[3], aAddr0 + ko);
        ldsm4(a1[0], a1[1], a1[2], a1[3], aAddr1 + ko);
        #pragma unroll
        for (int g = 0; g < 4; g++)
            ldsm4(bb[g][0], bb[g][1], bb[g][2], bb[g][3], bAddr + g * (16u * RSB) + ko);
        #pragma unroll
        for (int g = 0; g < 4; g++) {
            mma16816(acc[0][2 * g + 0], a0, bb[g][0], bb[g][1]);
            mma16816(acc[0][2 * g + 1], a0, bb[g][2], bb[g][3]);
            mma16816(acc[1][2 * g + 0], a1, bb[g][0], bb[g][1]);
            mma16816(acc[1][2 * g + 1], a1, bb[g][2], bb[g][3]);
        }
    }
}

// =====================================================================
// prep kernels
// =====================================================================
__global__ void __launch_bounds__(256)
convert_w_kernel(const float* __restrict__ Wk, const float* __restrict__ Wv,
                 const float* __restrict__ Wq, const float* __restrict__ Wo)
{
    __shared__ float tile[32][33];
    const int n0 = blockIdx.x * 32, k0 = blockIdx.y * 32;
    const float* W = (n0 < 256) ? Wk : (n0 < 512) ? Wv : (n0 < 768) ? Wq : Wo;
    const int ncol = n0 & 255;
    #pragma unroll
    for (int i = 0; i < 4; i++) {
        int k = k0 + threadIdx.y + i * 8;
        tile[threadIdx.y + i * 8][threadIdx.x] = W[k * 256 + ncol + threadIdx.x];
    }
    __syncthreads();
    #pragma unroll
    for (int i = 0; i < 4; i++) {
        int n = n0 + threadIdx.y + i * 8;
        g_Wt[(size_t)n * 256 + k0 + threadIdx.x] =
            __float2half(tile[threadIdx.x][threadIdx.y + i * 8]);
    }
}

__global__ void __launch_bounds__(256)
gather_xq_kernel(const float* __restrict__ X)
{
    int i = blockIdx.x * 256 + threadIdx.x;
    int row = i >> 7, cp = i & 127;
    int b = row >> 1, s = (row & 1) ? 127 : 63;
    float2 v = reinterpret_cast<const float2*>(X)[(((size_t)b * SS + s) * DD >> 1) + cp];
    reinterpret_cast<__half2*>(g_Xq)[i] = __floats2half2_rn(v.x, v.y);
}

// =====================================================================
// edge MLPs: 1 batch/block, 1024 blocks
// =====================================================================
__global__ void __launch_bounds__(256)
edge_kernel(const float* __restrict__ EF,
            const float* __restrict__ Wgate, const float* __restrict__ bgate,
            const float* __restrict__ Wscale, const float* __restrict__ bscale,
            const float* __restrict__ Wshift, const float* __restrict__ bshift,
            const float* __restrict__ Wbias, const float* __restrict__ bbias,
            const float* __restrict__ Whead, const float* __restrict__ bhead)
{
    __shared__ float ef[EE];
    const int b = blockIdx.x, t = threadIdx.x;
    if (t < EE) ef[t] = EF[(size_t)b * EE + t];
    __syncthreads();
    const int c = t;
    float ag = bgate[c], as = bscale[c], ah = bshift[c];
    #pragma unroll 8
    for (int e = 0; e < EE; e++) {
        const float f = ef[e];
        ag += f * Wgate[e * DD + c];
        as += f * Wscale[e * DD + c];
        ah += f * Wshift[e * DD + c];
    }
    const float gate = 1.0f / (1.0f + expf(-ag));
    g_a [b * DD + c] = gate * (1.0f + tanhf(as));
    g_s2[b * DD + c] = gate * ah;
    if (t < 8) {
        float acc = bbias[t];
        for (int e = 0; e < EE; e++) acc += ef[e] * Wbias[e * NHH + t];
        g_eb[b * NHH + t] = acc;
    } else if (t < 16) {
        const int h = t - 8;
        float acc = bhead[h];
        for (int e = 0; e < EE; e++) acc += ef[e] * Whead[e * NHH + h];
        g_hs[b * NHH + h] = (1.0f + tanhf(acc)) * INV_SQRT_HD;
    }
}

// =====================================================================
// Plain GEMM (mma.sync): mode0: g_Q = g_Xq @ WqT + bq
//                        mode1: out = g_AO @ WoT + bo
// =====================================================================
#define PG_A    0u
#define PG_B    (128u * RSB)
#define PG_SMEM (2 * 128 * RSB)

__global__ void __launch_bounds__(256)
gemm_mma_kernel(int mode, const float* __restrict__ bias, float* __restrict__ out_param)
{
    extern __shared__ __align__(16) char sm[];
    const unsigned smb = smem_u32(sm);
    const int t = threadIdx.x, w = t >> 5, lane = t & 31;
    const int m0 = blockIdx.x * 128;
    const int wm = (w & 3) * 32, wn = (w >> 2) * 64;
    const __half* Ag = mode ? g_AO : g_Xq;
    const __half* Bg = g_Wt + (size_t)(mode ? 768 : 512) * 256;
    float* out = mode ? out_param : g_Q;

    const uint4* As = reinterpret_cast<const uint4*>(Ag) + (size_t)m0 * 32;
    #pragma unroll
    for (int i = 0; i < 16; i++) {
        int idx = t + i * 256;
        int r = idx >> 5, c = idx & 31;
        *reinterpret_cast<uint4*>(sm + PG_A + (size_t)r * RSB + c * 16) = As[idx];
    }
    const unsigned Abase = smb + PG_A + (unsigned)wm * RSB;
    const unsigned Bbase = smb + PG_B + (unsigned)wn * RSB;

    for (int p = 0; p < 2; p++) {
        const uint4* Bs = reinterpret_cast<const uint4*>(Bg) + (size_t)p * 128 * 32;
        #pragma unroll
        for (int i = 0; i < 16; i++) {
            int idx = t + i * 256;
            int r = idx >> 5, c = idx & 31;
            *reinterpret_cast<uint4*>(sm + PG_B + (size_t)r * RSB + c * 16) = Bs[idx];
        }
        __syncthreads();

        float acc[2][8][4];
        #pragma unroll
        for (int mt = 0; mt < 2; mt++)
            #pragma unroll
            for (int nt = 0; nt < 8; nt++)
                #pragma unroll
                for (int e = 0; e < 4; e++) acc[mt][nt][e] = 0.0f;

        warp_gemm(acc, Abase, Bbase, lane);

        #pragma unroll
        for (int mt = 0; mt < 2; mt++) {
            #pragma unroll
            for (int nt = 0; nt < 8; nt++) {
                const int col = p * 128 + wn + nt * 8 + (lane & 3) * 2;
                const int r0 = m0 + wm + mt * 16 + (lane >> 2);
                const float b0 = bias[col], b1 = bias[col + 1];
                *reinterpret_cast<float2*>(&out[(size_t)r0 * DD + col]) =
                    make_float2(acc[mt][nt][0] + b0, acc[mt][nt][1] + b1);
                *reinterpret_cast<float2*>(&out[(size_t)(r0 + 8) * DD + col]) =
                    make_float2(acc[mt][nt][2] + b0, acc[mt][nt][3] + b1);
            }
        }
        __syncthreads();
    }
}

// =====================================================================
// FUSED: KV projection (mma.sync) + attention, one CTA per batch.
//   smem: sb(4KB) | qs(2KB) | eh | probs(8KB) | A(66K) | B/Vsh(66K) | Ksh(66K)
// =====================================================================
#define F_SB   0
#define F_QS   4096
#define F_EH   6144
#define F_PROB 6208
#define F_A    16384
#define F_B    (16384 + 128 * RSB)            // 83968; becomes Vsh
#define F_KS   (16384 + 2 * 128 * RSB)        // 151552
#define F_SMEM (16384 + 3 * 128 * RSB)        // 219136

__global__ void __launch_bounds__(256)
fused_kernel(const float* __restrict__ X,
             const float* __restrict__ bk, const float* __restrict__ bv)
{
    extern __shared__ __align__(16) char sm[];
    const unsigned smb = smem_u32(sm);
    float* sb  = reinterpret_cast<float*>(sm + F_SB);   // bk|bv|a|s2
    float* qsm = reinterpret_cast<float*>(sm + F_QS);
    float* eh  = reinterpret_cast<float*>(sm + F_EH);
    float* pr  = reinterpret_cast<float*>(sm + F_PROB);
    const int t = threadIdx.x, w = t >> 5, lane = t & 31;
    const int b = blockIdx.x;
    const int wm = (w & 3) * 32, wn = (w >> 2) * 64;

    sb[t]       = bk[t];
    sb[256 + t] = bv[t];
    sb[512 + t] = g_a [b * DD + t];
    sb[768 + t] = g_s2[b * DD + t];
    qsm[t]       = g_Q[((size_t)b * 2 + 0) * DD + t];
    qsm[256 + t] = g_Q[((size_t)b * 2 + 1) * DD + t];
    if (t < 8)       eh[t] = g_eb[b * NHH + t];
    else if (t < 16) eh[t] = g_hs[b * NHH + (t - 8)];

    // A: X_b fp32 -> fp16 smem
    const float4* X4 = reinterpret_cast<const float4*>(X) + (size_t)b * SS * 64;
    #pragma unroll
    for (int i = 0; i < 32; i++) {
        int idx = t + i * 256;
        int r = idx >> 6, kq = idx & 63;
        float4 v = X4[idx];
        __half2 h0 = __floats2half2_rn(v.x, v.y);
        __half2 h1 = __floats2half2_rn(v.z, v.w);
        uint2 pk;
        pk.x = *reinterpret_cast<unsigned*>(&h0);
        pk.y = *reinterpret_cast<unsigned*>(&h1);
        *reinterpret_cast<uint2*>(sm + F_A + (size_t)r * RSB + kq * 8) = pk;
    }
    // B pass0
    const uint4* Wsrc = reinterpret_cast<const uint4*>(g_Wt);
    #pragma unroll
    for (int i = 0; i < 16; i++) {
        int idx = t + i * 256;
        int r = idx >> 5, c = idx & 31;
        *reinterpret_cast<uint4*>(sm + F_B + (size_t)r * RSB + c * 16) = Wsrc[idx];
    }
    __syncthreads();

    const unsigned Abase = smb + F_A + (unsigned)wm * RSB;
    const unsigned Bbase = smb + F_B + (unsigned)wn * RSB;
    unsigned vkeep[2][8][2];   // pass-2 V (gated fp16), held in regs
    unsigned vk2[2][8][2];     // pass-3 V

    #pragma unroll
    for (int p = 0; p < 4; p++) {
        uint4 rb[16];
        if (p < 3) {
            const uint4* src = Wsrc + (size_t)(p + 1) * 4096;
            #pragma unroll
            for (int i = 0; i < 16; i++) rb[i] = src[t + i * 256];
        }
        float acc[2][8][4];
        #pragma unroll
        for (int mt = 0; mt < 2; mt++)
            #pragma unroll
            for (int nt = 0; nt < 8; nt++)
                #pragma unroll
                for (int e = 0; e < 4; e++) acc[mt][nt][e] = 0.0f;

        warp_gemm(acc, Abase, Bbase, lane);

        if (p < 2) {
            // K epilogue -> Ksh
            #pragma unroll
            for (int mt = 0; mt < 2; mt++)
                #pragma unroll
                for (int nt = 0; nt < 8; nt++) {
                    const int col = p * 128 + wn + nt * 8 + (lane & 3) * 2;
                    const int r0 = wm + mt * 16 + (lane >> 2);
                    const float b0 = sb[col], b1 = sb[col + 1];
                    *reinterpret_cast<__half2*>(sm + F_KS + (size_t)r0 * RSB + col * 2) =
                        __floats2half2_rn(acc[mt][nt][0] + b0, acc[mt][nt][1] + b1);
                    *reinterpret_cast<__half2*>(sm + F_KS + (size_t)(r0 + 8) * RSB + col * 2) =
                        __floats2half2_rn(acc[mt][nt][2] + b0, acc[mt][nt][3] + b1);
                }
        } else {
            // V epilogue: gate, pack to regs
            #pragma unroll
            for (int mt = 0; mt < 2; mt++)
                #pragma unroll
                for (int nt = 0; nt < 8; nt++) {
                    const int col = (p - 2) * 128 + wn + nt * 8 + (lane & 3) * 2;
                    const float b0 = sb[256 + col], b1 = sb[256 + col + 1];
                    const float a0 = sb[512 + col], a1 = sb[512 + col + 1];
                    const float s0 = sb[768 + col], s1 = sb[768 + col + 1];
                    __half2 h01 = __floats2half2_rn((acc[mt][nt][0] + b0) * a0 + s0,
                                                    (acc[mt][nt][1] + b1) * a1 + s1);
                    __half2 h23 = __floats2half2_rn((acc[mt][nt][2] + b0) * a0 + s0,
                                                    (acc[mt][nt][3] + b1) * a1 + s1);
                    if (p == 2) {
                        vkeep[mt][nt][0] = *reinterpret_cast<unsigned*>(&h01);
                        vkeep[mt][nt][1] = *reinterpret_cast<unsigned*>(&h23);
                    } else {
                        vk2[mt][nt][0] = *reinterpret_cast<unsigned*>(&h01);
                        vk2[mt][nt][1] = *reinterpret_cast<unsigned*>(&h23);
                    }
                }
        }
        __syncthreads();                 // all warps done reading B
        if (p < 3) {
            #pragma unroll
            for (int i = 0; i < 16; i++) {
                int idx = t + i * 256;
                int r = idx >> 5, c = idx & 31;
                *reinterpret_cast<uint4*>(sm + F_B + (size_t)r * RSB + c * 16) = rb[i];
            }
            __syncthreads();
        }
    }

    // write held V into B region (now Vsh)
    #pragma unroll
    for (int mt = 0; mt < 2; mt++)
        #pragma unroll
        for (int nt = 0; nt < 8; nt++) {
            const int col0 = wn + nt * 8 + (lane & 3) * 2;
            const int r0 = wm + mt * 16 + (lane >> 2);
            *reinterpret_cast<unsigned*>(sm + F_B + (size_t)r0 * RSB + col0 * 2) = vkeep[mt][nt][0];
            *reinterpret_cast<unsigned*>(sm + F_B + (size_t)(r0 + 8) * RSB + col0 * 2) = vkeep[mt][nt][1];
            const int col1 = 128 + col0;
            *reinterpret_cast<unsigned*>(sm + F_B + (size_t)r0 * RSB + col1 * 2) = vk2[mt][nt][0];
            *reinterpret_cast<unsigned*>(sm + F_B + (size_t)(r0 + 8) * RSB + col1 * 2) = vk2[mt][nt][1];
        }
    __syncthreads();

    // ---- attention: warp w = head w ----
    #pragma unroll
    for (int qi = 0; qi < 2; qi++) {
        float sv[4];
        const int kb = qi ? 63 : 127;
        #pragma unroll
        for (int j = 0; j < 4; j++) {
            const int k = lane + 32 * j;
            const __half2* kr = reinterpret_cast<const __half2*>(
                sm + F_KS + (size_t)k * RSB + (w * HDD) * 2);
            const float* qp = &qsm[qi * 256 + w * HDD];
            float acc = 0.0f;
            #pragma unroll
            for (int d2 = 0; d2 < 16; d2++) {
                float2 kv = __half22float2(kr[d2]);
                acc += qp[2 * d2] * kv.x + qp[2 * d2 + 1] * kv.y;
            }
            float s = acc * eh[8 + w];
            if (k == kb) s += eh[w];
            sv[j] = s;
        }
        float m = fmaxf(fmaxf(sv[0], sv[1]), fmaxf(sv[2], sv[3]));
        #pragma unroll
        for (int o = 16; o > 0; o >>= 1) m = fmaxf(m, __shfl_xor_sync(0xffffffffu, m, o));
        float e[4], sum = 0.0f;
        #pragma unroll
        for (int j = 0; j < 4; j++) { e[j] = expf(sv[j] - m); sum += e[j]; }
        #pragma unroll
        for (int o = 16; o > 0; o >>= 1) sum += __shfl_xor_sync(0xffffffffu, sum, o);
        const float inv = 1.0f / sum;
        #pragma unroll
        for (int j = 0; j < 4; j++) pr[(w * 2 + qi) * SS + lane + 32 * j] = e[j] * inv;
    }
    __syncthreads();

    // AV from Vsh
    const int p = t >> 4, dp = t & 15;
    const int h = p >> 1, qi = p & 1;
    const int col = h * HDD + dp * 2;
    float ax = 0.0f, ay = 0.0f;
    const float* prow = &pr[p * SS];
    #pragma unroll 4
    for (int k = 0; k < SS; k++) {
        const float a = prow[k];
        float2 v = __half22float2(
            *reinterpret_cast<const __half2*>(sm + F_B + (size_t)k * RSB + col * 2));
        ax += a * v.x; ay += a * v.y;
    }
    *reinterpret_cast<__half2*>(&g_AO[((size_t)b * 2 + qi) * DD + col]) =
        __floats2half2_rn(ax, ay);
}

// =====================================================================
extern "C" void kernel_launch(void* const* d_in, const int* in_sizes, int n_in,
                              void* d_out, int out_size)
{
    (void)in_sizes; (void)n_in; (void)out_size;
    const float* X      = (const float*)d_in[0];
    const float* EF     = (const float*)d_in[1];
    const float* Wq     = (const float*)d_in[2];
    const float* bq     = (const float*)d_in[3];
    const float* Wk     = (const float*)d_in[4];
    const float* bk     = (const float*)d_in[5];
    const float* Wv     = (const float*)d_in[6];
    const float* bv     = (const float*)d_in[7];
    const float* Wo     = (const float*)d_in[8];
    const float* bo     = (const float*)d_in[9];
    const float* Wbias  = (const float*)d_in[10];
    const float* bbias  = (const float*)d_in[11];
    const float* Wgate  = (const float*)d_in[12];
    const float* bgate  = (const float*)d_in[13];
    const float* Wscale = (const float*)d_in[14];
    const float* bscale = (const float*)d_in[15];
    const float* Wshift = (const float*)d_in[16];
    const float* bshift = (const float*)d_in[17];
    const float* Whead  = (const float*)d_in[18];
    const float* bhead  = (const float*)d_in[19];
    float* out = (float*)d_out;

    cudaFuncSetAttribute(fused_kernel,
                         cudaFuncAttributeMaxDynamicSharedMemorySize, F_SMEM);
    cudaFuncSetAttribute(gemm_mma_kernel,
                         cudaFuncAttributeMaxDynamicSharedMemorySize, PG_SMEM);

    convert_w_kernel<<<dim3(32, 8), dim3(32, 8)>>>(Wk, Wv, Wq, Wo);
    gather_xq_kernel<<<1024, 256>>>(X);
    edge_kernel<<<1024, 256>>>(EF, Wgate, bgate, Wscale, bscale,
                               Wshift, bshift, Wbias, bbias, Whead, bhead);
    gemm_mma_kernel<<<16, 256, PG_SMEM>>>(0, bq, nullptr);
    fused_kernel<<<1024, 256, F_SMEM>>>(X, bk, bv);
    gemm_mma_kernel<<<16, 256, PG_SMEM>>>(1, bo, out);
}

// round 7
// speedup vs baseline: 12.8344x; 1.9176x over previous
#include <cuda_runtime.h>
#include <cuda_fp16.h>
#include <math.h>

#define BB 1024
#define SS 128
#define DD 256
#define EE 128
#define NHH 8
#define INV_SQRT_HD 0.17677669529663687f
#define RSB 528                 // 264-half pitch (bytes)

// ---------------- device scratch ----------------
__device__ __align__(16) __half g_Wt [1024 * 256];  // [WkT|WvT|WqT|WoT] fp16 [n][k]
__device__ __align__(16) __half g_Wkn[256 * 256];   // Wk plain fp16 [k][n]
__device__ __align__(16) __half g_Xq [2048 * 256];
__device__ __align__(16) __half g_Qh [2048 * 256];  // Q projected fp16
__device__ __align__(16) __half g_R  [(size_t)BB * 16 * 256];
__device__ __align__(16) __half g_Y  [(size_t)BB * 16 * 256];
__device__ __align__(16) __half g_AO [2048 * 256];
__device__ __align__(16) float  g_bkd[BB * 16];
__device__ __align__(16) float  g_a  [BB * DD];
__device__ __align__(16) float  g_s2 [BB * DD];
__device__ __align__(16) float  g_eb [BB * NHH];
__device__ __align__(16) float  g_hs [BB * NHH];

// ---------------- helpers ----------------
__device__ __forceinline__ unsigned smem_u32(const void* p) {
    unsigned a;
    asm("{ .reg .u64 t; cvta.to.shared.u64 t, %1; cvt.u32.u64 %0, t; }" : "=r"(a) : "l"(p));
    return a;
}
__device__ __forceinline__ void ldsm4(unsigned* r, unsigned a) {
    asm volatile("ldmatrix.sync.aligned.m8n8.x4.shared.b16 {%0,%1,%2,%3}, [%4];"
                 : "=r"(r[0]), "=r"(r[1]), "=r"(r[2]), "=r"(r[3]) : "r"(a));
}
__device__ __forceinline__ void ldsm4t(unsigned* r, unsigned a) {
    asm volatile("ldmatrix.sync.aligned.m8n8.x4.trans.shared.b16 {%0,%1,%2,%3}, [%4];"
                 : "=r"(r[0]), "=r"(r[1]), "=r"(r[2]), "=r"(r[3]) : "r"(a));
}
__device__ __forceinline__ void mma16816(float c[4], const unsigned a[4],
                                         unsigned b0, unsigned b1) {
    asm volatile("mma.sync.aligned.m16n8k16.row.col.f32.f16.f16.f32 "
        "{%0,%1,%2,%3}, {%4,%5,%6,%7}, {%8,%9}, {%0,%1,%2,%3};"
        : "+f"(c[0]), "+f"(c[1]), "+f"(c[2]), "+f"(c[3])
        : "r"(a[0]), "r"(a[1]), "r"(a[2]), "r"(a[3]), "r"(b0), "r"(b1));
}

// =====================================================================
// prep
// =====================================================================
__global__ void __launch_bounds__(256)
convert_w_kernel(const float* __restrict__ Wk, const float* __restrict__ Wv,
                 const float* __restrict__ Wq, const float* __restrict__ Wo)
{
    __shared__ float tile[32][33];
    const int n0 = blockIdx.x * 32, k0 = blockIdx.y * 32;
    const float* W = (n0 < 256) ? Wk : (n0 < 512) ? Wv : (n0 < 768) ? Wq : Wo;
    const int ncol = n0 & 255;
    #pragma unroll
    for (int i = 0; i < 4; i++) {
        int k = k0 + threadIdx.y + i * 8;
        tile[threadIdx.y + i * 8][threadIdx.x] = W[k * 256 + ncol + threadIdx.x];
    }
    __syncthreads();
    #pragma unroll
    for (int i = 0; i < 4; i++) {
        int n = n0 + threadIdx.y + i * 8;
        g_Wt[(size_t)n * 256 + k0 + threadIdx.x] =
            __float2half(tile[threadIdx.x][threadIdx.y + i * 8]);
    }
}

__global__ void __launch_bounds__(256)
convert_wkn_kernel(const float* __restrict__ Wk)
{
    int i = blockIdx.x * 256 + threadIdx.x;       // 32768 half2
    float2 v = reinterpret_cast<const float2*>(Wk)[i];
    reinterpret_cast<__half2*>(g_Wkn)[i] = __floats2half2_rn(v.x, v.y);
}

__global__ void __launch_bounds__(256)
gather_xq_kernel(const float* __restrict__ X)
{
    int i = blockIdx.x * 256 + threadIdx.x;
    int row = i >> 7, cp = i & 127;
    int b = row >> 1, s = (row & 1) ? 127 : 63;
    float2 v = reinterpret_cast<const float2*>(X)[(((size_t)b * SS + s) * DD >> 1) + cp];
    reinterpret_cast<__half2*>(g_Xq)[i] = __floats2half2_rn(v.x, v.y);
}

// =====================================================================
// edge MLPs
// =====================================================================
__global__ void __launch_bounds__(256)
edge_kernel(const float* __restrict__ EF,
            const float* __restrict__ Wgate, const float* __restrict__ bgate,
            const float* __restrict__ Wscale, const float* __restrict__ bscale,
            const float* __restrict__ Wshift, const float* __restrict__ bshift,
            const float* __restrict__ Wbias, const float* __restrict__ bbias,
            const float* __restrict__ Whead, const float* __restrict__ bhead)
{
    __shared__ float ef[EE];
    const int b = blockIdx.x, t = threadIdx.x;
    if (t < EE) ef[t] = EF[(size_t)b * EE + t];
    __syncthreads();
    float ag = bgate[t], as = bscale[t], ah = bshift[t];
    #pragma unroll 8
    for (int e = 0; e < EE; e++) {
        const float f = ef[e];
        ag += f * Wgate[e * DD + t];
        as += f * Wscale[e * DD + t];
        ah += f * Wshift[e * DD + t];
    }
    const float gate = 1.0f / (1.0f + expf(-ag));
    g_a [b * DD + t] = gate * (1.0f + tanhf(as));
    g_s2[b * DD + t] = gate * ah;
    if (t < 8) {
        float acc = bbias[t];
        for (int e = 0; e < EE; e++) acc += ef[e] * Wbias[e * NHH + t];
        g_eb[b * NHH + t] = acc;
    } else if (t < 16) {
        const int h = t - 8;
        float acc = bhead[h];
        for (int e = 0; e < EE; e++) acc += ef[e] * Whead[e * NHH + h];
        g_hs[b * NHH + h] = (1.0f + tanhf(acc)) * INV_SQRT_HD;
    }
}

// =====================================================================
// gemm32: C[2048][256] = A @ WtSlice + bias.  M-tile 32, N-tile 128.
//   mode0: A=g_Xq, W=WqT -> g_Qh fp16.  mode1: A=g_AO, W=WoT -> out fp32.
// =====================================================================
#define G32_B    16896u
#define G32_SMEM (16896 + 128 * RSB)

__global__ void __launch_bounds__(256)
gemm32_kernel(int mode, const float* __restrict__ bias, float* __restrict__ outp)
{
    extern __shared__ __align__(16) char sm[];
    const unsigned smb = smem_u32(sm);
    const int t = threadIdx.x, w = t >> 5, lane = t & 31;
    const int m0 = blockIdx.x * 32, ny = blockIdx.y;
    const __half* Ag = mode ? g_AO : g_Xq;
    const __half* Bg = g_Wt + (size_t)((mode ? 768 : 512) + ny * 128) * 256;

    #pragma unroll
    for (int i = 0; i < 4; i++) {
        int idx = t + i * 256;                  // 1024 uint4 (A: 32x256)
        int r = idx >> 5, c = idx & 31;
        *reinterpret_cast<uint4*>(sm + (size_t)r * RSB + c * 16) =
            reinterpret_cast<const uint4*>(Ag + (size_t)(m0 + r) * 256)[c];
    }
    #pragma unroll
    for (int i = 0; i < 16; i++) {
        int idx = t + i * 256;                  // 4096 uint4 (B: 128x256)
        int r = idx >> 5, c = idx & 31;
        *reinterpret_cast<uint4*>(sm + G32_B + (size_t)r * RSB + c * 16) =
            reinterpret_cast<const uint4*>(Bg + (size_t)r * 256)[c];
    }
    __syncthreads();

    const int wm = (w & 1) * 16, wn = (w >> 1) * 32;
    float acc[4][4];
    #pragma unroll
    for (int n = 0; n < 4; n++)
        #pragma unroll
        for (int e = 0; e < 4; e++) acc[n][e] = 0.0f;
    const unsigned aA = smb + (unsigned)(wm + (lane & 15)) * RSB + (lane >> 4) * 16;
    const unsigned bA = smb + G32_B + (unsigned)(wn + (lane & 7) + ((lane >> 4) << 3)) * RSB
                        + ((lane >> 3) & 1) * 16;
    #pragma unroll
    for (int ks = 0; ks < 16; ks++) {
        const unsigned ko = ks * 32u;
        unsigned a[4], bb[4];
        ldsm4(a, aA + ko);
        #pragma unroll
        for (int g = 0; g < 2; g++) {
            ldsm4(bb, bA + g * (16u * RSB) + ko);
            mma16816(acc[2 * g],     a, bb[0], bb[1]);
            mma16816(acc[2 * g + 1], a, bb[2], bb[3]);
        }
    }
    #pragma unroll
    for (int nt = 0; nt < 4; nt++) {
        const int col = ny * 128 + wn + nt * 8 + (lane & 3) * 2;
        const int r0 = m0 + wm + (lane >> 2);
        const float b0 = bias[col], b1 = bias[col + 1];
        if (mode == 0) {
            *reinterpret_cast<__half2*>(&g_Qh[(size_t)r0 * 256 + col]) =
                __floats2half2_rn(acc[nt][0] + b0, acc[nt][1] + b1);
            *reinterpret_cast<__half2*>(&g_Qh[(size_t)(r0 + 8) * 256 + col]) =
                __floats2half2_rn(acc[nt][2] + b0, acc[nt][3] + b1);
        } else {
            *reinterpret_cast<float2*>(&outp[(size_t)r0 * 256 + col]) =
                make_float2(acc[nt][0] + b0, acc[nt][1] + b1);
            *reinterpret_cast<float2*>(&outp[(size_t)(r0 + 8) * 256 + col]) =
                make_float2(acc[nt][2] + b0, acc[nt][3] + b1);
        }
    }
}

// =====================================================================
// r kernel: R[(b,p)][c] = sum_d Qh[rq][h32+d] * Wk[c][h32+d];  + bkdot.
//   grid (32, 8): 64 rq-rows x head.  K=32.
// =====================================================================
__global__ void __launch_bounds__(256)
r_kernel(const float* __restrict__ bk)
{
    __shared__ __align__(16) __half As[64 * 40];    // pitch 80B
    __shared__ __align__(16) __half Bs[256 * 40];
    const int t = threadIdx.x, w = t >> 5, lane = t & 31;
    const int m0 = blockIdx.x * 64, h = blockIdx.y;

    {   // A: Qh[m0..m0+64][h32..h32+32]
        int r = t >> 2, c4 = t & 3;
        reinterpret_cast<uint4*>(As + r * 40)[c4] =
            reinterpret_cast<const uint4*>(g_Qh + (size_t)(m0 + r) * 256 + h * 32)[c4];
    }
    #pragma unroll
    for (int i = 0; i < 4; i++) {   // B: Wkn[0..256][h32..h32+32]
        int idx = t + i * 256;
        int r = idx >> 2, c4 = idx & 3;
        reinterpret_cast<uint4*>(Bs + r * 40)[c4] =
            reinterpret_cast<const uint4*>(g_Wkn + (size_t)r * 256 + h * 32)[c4];
    }
    __syncthreads();

    if (t < 64) {
        float s = 0.0f;
        #pragma unroll
        for (int d = 0; d < 32; d++)
            s += __half2float(As[t * 40 + d]) * bk[h * 32 + d];
        g_bkd[(size_t)((m0 + t) >> 1) * 16 + h * 2 + ((m0 + t) & 1)] = s;
    }

    const int wm = (w & 3) * 16, wn = (w >> 2) * 128;
    float acc[16][4];
    #pragma unroll
    for (int n = 0; n < 16; n++)
        #pragma unroll
        for (int e = 0; e < 4; e++) acc[n][e] = 0.0f;
    const unsigned aA = smem_u32(As) + (unsigned)(wm + (lane & 15)) * 80 + (lane >> 4) * 16;
    const unsigned bA = smem_u32(Bs) + (unsigned)(wn + (lane & 7) + ((lane >> 4) << 3)) * 80
                        + ((lane >> 3) & 1) * 16;
    #pragma unroll
    for (int ks = 0; ks < 2; ks++) {
        const unsigned ko = ks * 32u;
        unsigned a[4];
        ldsm4(a, aA + ko);
        #pragma unroll
        for (int g = 0; g < 8; g++) {
            unsigned bb[4];
            ldsm4(bb, bA + g * (16u * 80) + ko);
            mma16816(acc[2 * g],     a, bb[0], bb[1]);
            mma16816(acc[2 * g + 1], a, bb[2], bb[3]);
        }
    }
    #pragma unroll
    for (int nt = 0; nt < 16; nt++) {
        const int c = wn + nt * 8 + (lane & 3) * 2;
        #pragma unroll
        for (int half_ = 0; half_ < 2; half_++) {
            const int rr = m0 + wm + (lane >> 2) + half_ * 8;
            const int bidx = rr >> 1, p = h * 2 + (rr & 1);
            *reinterpret_cast<__half2*>(&g_R[((size_t)bidx * 16 + p) * 256 + c]) =
                __floats2half2_rn(acc[nt][2 * half_], acc[nt][2 * half_ + 1]);
        }
    }
}

// =====================================================================
// FUSED: scores (R @ XhT) + softmax + y (P @ X via ldsm.trans) per batch.
// =====================================================================
#define FX_XH   0
#define FX_R    67584
#define FX_P    (67584 + 8448)             // 76032, pitch 272
#define FX_S    (76032 + 8704)             // 84736, fp32 16x128
#define FX_MISC (84736 + 8192)             // 92928
#define FX_SMEM (92928 + 128)

__global__ void __launch_bounds__(256, 2)
fused_kernel(const float* __restrict__ X)
{
    extern __shared__ __align__(16) char sm[];
    const unsigned smb = smem_u32(sm);
    float* S   = reinterpret_cast<float*>(sm + FX_S);
    float* msc = reinterpret_cast<float*>(sm + FX_MISC);  // eb[8] hsv[8] bkd[16]
    const int t = threadIdx.x, w = t >> 5, lane = t & 31;
    const int b = blockIdx.x;

    if (t < 8)       msc[t] = g_eb[b * NHH + t];
    else if (t < 16) msc[t] = g_hs[b * NHH + (t - 8)];
    else if (t < 32) msc[t] = g_bkd[(size_t)b * 16 + (t - 16)];

    #pragma unroll
    for (int i = 0; i < 2; i++) {       // R: 16x256 fp16
        int idx = t + i * 256;
        int r = idx >> 5, c = idx & 31;
        *reinterpret_cast<uint4*>(sm + FX_R + (size_t)r * RSB + c * 16) =
            reinterpret_cast<const uint4*>(g_R + ((size_t)b * 16 + r) * 256)[c];
    }
    const float4* X4 = reinterpret_cast<const float4*>(X) + (size_t)b * SS * 64;
    #pragma unroll
    for (int i = 0; i < 32; i++) {      // Xh: 128x256 fp16
        int idx = t + i * 256;
        int r = idx >> 6, kq = idx & 63;
        float4 v = X4[idx];
        __half2 h0 = __floats2half2_rn(v.x, v.y);
        __half2 h1 = __floats2half2_rn(v.z, v.w);
        uint2 pk;
        pk.x = *reinterpret_cast<unsigned*>(&h0);
        pk.y = *reinterpret_cast<unsigned*>(&h1);
        *reinterpret_cast<uint2*>(sm + FX_XH + (size_t)r * RSB + kq * 8) = pk;
    }
    __syncthreads();

    // ---- scores: S[16][128] = R @ Xh^T;  warp w = keys [w*16, w*16+16) ----
    {
        float sa[2][4];
        #pragma unroll
        for (int n = 0; n < 2; n++)
            #pragma unroll
            for (int e = 0; e < 4; e++) sa[n][e] = 0.0f;
        const unsigned aA = smb + FX_R + (unsigned)(lane & 15) * RSB + (lane >> 4) * 16;
        const unsigned bA = smb + FX_XH + (unsigned)(w * 16 + (lane & 7) + ((lane >> 4) << 3)) * RSB
                            + ((lane >> 3) & 1) * 16;
        #pragma unroll
        for (int ks = 0; ks < 16; ks++) {
            const unsigned ko = ks * 32u;
            unsigned a[4], bb[4];
            ldsm4(a, aA + ko);
            ldsm4(bb, bA + ko);
            mma16816(sa[0], a, bb[0], bb[1]);
            mma16816(sa[1], a, bb[2], bb[3]);
        }
        #pragma unroll
        for (int nt = 0; nt < 2; nt++) {
            const int c0 = w * 16 + nt * 8 + (lane & 3) * 2;
            const int p0 = lane >> 2;
            S[p0 * 128 + c0]           = sa[nt][0];
            S[p0 * 128 + c0 + 1]       = sa[nt][1];
            S[(p0 + 8) * 128 + c0]     = sa[nt][2];
            S[(p0 + 8) * 128 + c0 + 1] = sa[nt][3];
        }
    }
    __syncthreads();

    // ---- softmax: warp w = head w ----
    #pragma unroll
    for (int qi = 0; qi < 2; qi++) {
        const int p = w * 2 + qi;
        const int kb = qi ? 63 : 127;
        float sv[4];
        #pragma unroll
        for (int j = 0; j < 4; j++) {
            const int k = lane + 32 * j;
            float s = (S[p * 128 + k] + msc[16 + p]) * msc[8 + w];
            if (k == kb) s += msc[w];
            sv[j] = s;
        }
        float m = fmaxf(fmaxf(sv[0], sv[1]), fmaxf(sv[2], sv[3]));
        #pragma unroll
        for (int o = 16; o > 0; o >>= 1) m = fmaxf(m, __shfl_xor_sync(0xffffffffu, m, o));
        float e[4], sum = 0.0f;
        #pragma unroll
        for (int j = 0; j < 4; j++) { e[j] = expf(sv[j] - m); sum += e[j]; }
        #pragma unroll
        for (int o = 16; o > 0; o >>= 1) sum += __shfl_xor_sync(0xffffffffu, sum, o);
        const float inv = 1.0f / sum;
        #pragma unroll
        for (int j = 0; j < 4; j++) {
            const int k = lane + 32 * j;
            const float pv = e[j] * inv;
            const __half hi = __float2half_rn(pv);
            const __half lo = __float2half_rn(pv - __half2float(hi));
            *reinterpret_cast<__half*>(sm + FX_P + (size_t)p * 272 + k * 2) = hi;
            *reinterpret_cast<__half*>(sm + FX_P + (size_t)(p + 16) * 272 + k * 2) = lo;
        }
    }
    __syncthreads();

    // ---- y: [Phi;Plo](32x128) @ X(128x256); warp w = cols [w*32, w*32+32) ----
    {
        float ya[2][4][4];
        #pragma unroll
        for (int mt = 0; mt < 2; mt++)
            #pragma unroll
            for (int n = 0; n < 4; n++)
                #pragma unroll
                for (int e = 0; e < 4; e++) ya[mt][n][e] = 0.0f;
        const unsigned pA = smb + FX_P + (unsigned)(lane & 15) * 272 + (lane >> 4) * 16;
        const unsigned bT = smb + FX_XH
            + (unsigned)((lane & 7) + ((lane >> 3) & 1) * 8) * RSB
            + (lane >> 4) * 16 + (unsigned)(w * 32) * 2;
        #pragma unroll
        for (int ks = 0; ks < 8; ks++) {
            unsigned a0[4], a1[4], b0[4], b1[4];
            ldsm4(a0, pA + ks * 32u);
            ldsm4(a1, pA + 16u * 272 + ks * 32u);
            ldsm4t(b0, bT + ks * (16u * RSB));
            ldsm4t(b1, bT + 32u + ks * (16u * RSB));
            mma16816(ya[0][0], a0, b0[0], b0[1]);
            mma16816(ya[0][1], a0, b0[2], b0[3]);
            mma16816(ya[0][2], a0, b1[0], b1[1]);
            mma16816(ya[0][3], a0, b1[2], b1[3]);
            mma16816(ya[1][0], a1, b0[0], b0[1]);
            mma16816(ya[1][1], a1, b0[2], b0[3]);
            mma16816(ya[1][2], a1, b1[0], b1[1]);
            mma16816(ya[1][3], a1, b1[2], b1[3]);
        }
        #pragma unroll
        for (int nt = 0; nt < 4; nt++) {
            const int c0 = w * 32 + nt * 8 + (lane & 3) * 2;
            const int p0 = lane >> 2;
            float y00 = ya[0][nt][0] + ya[1][nt][0];
            float y01 = ya[0][nt][1] + ya[1][nt][1];
            float y10 = ya[0][nt][2] + ya[1][nt][2];
            float y11 = ya[0][nt][3] + ya[1][nt][3];
            *reinterpret_cast<__half2*>(&g_Y[((size_t)b * 16 + p0) * 256 + c0]) =
                __floats2half2_rn(y00, y01);
            *reinterpret_cast<__half2*>(&g_Y[((size_t)b * 16 + p0 + 8) * 256 + c0]) =
                __floats2half2_rn(y10, y11);
        }
    }
}

// =====================================================================
// AOh: per-head GEMM  AO[rq][h32+d] = a*(Y_h @ WvT_h + bv) + s2
//   grid (32, 8): 32 batches (64 rq rows) x head.
// =====================================================================
#define AO_B    33792u
#define AO_SMEM (33792 + 32 * RSB)

__global__ void __launch_bounds__(256)
aoh_kernel(const float* __restrict__ bv)
{
    extern __shared__ __align__(16) char sm[];
    const unsigned smb = smem_u32(sm);
    const int t = threadIdx.x, w = t >> 5, lane = t & 31;
    const int b0 = blockIdx.x * 32, h = blockIdx.y;

    #pragma unroll
    for (int i = 0; i < 8; i++) {       // A: Y rows (b, h, qi): 64x256
        int idx = t + i * 256;
        int rr = idx >> 5, c = idx & 31;
        const size_t src = ((size_t)(b0 + (rr >> 1)) * 16 + h * 2 + (rr & 1)) * 256;
        *reinterpret_cast<uint4*>(sm + (size_t)rr * RSB + c * 16) =
            reinterpret_cast<const uint4*>(g_Y + src)[c];
    }
    #pragma unroll
    for (int i = 0; i < 4; i++) {       // B: WvT rows 256+h32 .. +32
        int idx = t + i * 256;
        int r = idx >> 5, c = idx & 31;
        *reinterpret_cast<uint4*>(sm + AO_B + (size_t)r * RSB + c * 16) =
            reinterpret_cast<const uint4*>(g_Wt + (size_t)(256 + h * 32 + r) * 256)[c];
    }
    __syncthreads();

    const int wm = (w & 3) * 16, wn = (w >> 2) * 16;
    float acc[2][4];
    #pragma unroll
    for (int n = 0; n < 2; n++)
        #pragma unroll
        for (int e = 0; e < 4; e++) acc[n][e] = 0.0f;
    const unsigned aA = smb + (unsigned)(wm + (lane & 15)) * RSB + (lane >> 4) * 16;
    const unsigned bA = smb + AO_B + (unsigned)(wn + (lane & 7) + ((lane >> 4) << 3)) * RSB
                        + ((lane >> 3) & 1) * 16;
    #pragma unroll
    for (int ks = 0; ks < 16; ks++) {
        const unsigned ko = ks * 32u;
        unsigned a[4], bb[4];
        ldsm4(a, aA + ko);
        ldsm4(bb, bA + ko);
        mma16816(acc[0], a, bb[0], bb[1]);
        mma16816(acc[1], a, bb[2], bb[3]);
    }
    #pragma unroll
    for (int nt = 0; nt < 2; nt++) {
        const int col = wn + nt * 8 + (lane & 3) * 2;
        const int C = h * 32 + col;
        const float b0f = bv[C], b1f = bv[C + 1];
        #pragma unroll
        for (int half_ = 0; half_ < 2; half_++) {
            const int rr = wm + (lane >> 2) + half_ * 8;
            const int bb_ = b0 + (rr >> 1), qi = rr & 1;
            const float a0 = g_a[bb_ * DD + C],  a1 = g_a[bb_ * DD + C + 1];
            const float s0 = g_s2[bb_ * DD + C], s1 = g_s2[bb_ * DD + C + 1];
            const float v0 = (acc[nt][2 * half_]     + b0f) * a0 + s0;
            const float v1 = (acc[nt][2 * half_ + 1] + b1f) * a1 + s1;
            *reinterpret_cast<__half2*>(&g_AO[(size_t)(bb_ * 2 + qi) * 256 + C]) =
                __floats2half2_rn(v0, v1);
        }
    }
}

// =====================================================================
extern "C" void kernel_launch(void* const* d_in, const int* in_sizes, int n_in,
                              void* d_out, int out_size)
{
    (void)in_sizes; (void)n_in; (void)out_size;
    const float* X      = (const float*)d_in[0];
    const float* EF     = (const float*)d_in[1];
    const float* Wq     = (const float*)d_in[2];
    const float* bq     = (const float*)d_in[3];
    const float* Wk     = (const float*)d_in[4];
    const float* bk     = (const float*)d_in[5];
    const float* Wv     = (const float*)d_in[6];
    const float* bv     = (const float*)d_in[7];
    const float* Wo     = (const float*)d_in[8];
    const float* bo     = (const float*)d_in[9];
    const float* Wbias  = (const float*)d_in[10];
    const float* bbias  = (const float*)d_in[11];
    const float* Wgate  = (const float*)d_in[12];
    const float* bgate  = (const float*)d_in[13];
    const float* Wscale = (const float*)d_in[14];
    const float* bscale = (const float*)d_in[15];
    const float* Wshift = (const float*)d_in[16];
    const float* bshift = (const float*)d_in[17];
    const float* Whead  = (const float*)d_in[18];
    const float* bhead  = (const float*)d_in[19];
    float* out = (float*)d_out;

    cudaFuncSetAttribute(gemm32_kernel, cudaFuncAttributeMaxDynamicSharedMemorySize, G32_SMEM);
    cudaFuncSetAttribute(fused_kernel,  cudaFuncAttributeMaxDynamicSharedMemorySize, FX_SMEM);
    cudaFuncSetAttribute(aoh_kernel,    cudaFuncAttributeMaxDynamicSharedMemorySize, AO_SMEM);

    convert_w_kernel<<<dim3(32, 8), dim3(32, 8)>>>(Wk, Wv, Wq, Wo);
    convert_wkn_kernel<<<128, 256>>>(Wk);
    gather_xq_kernel<<<1024, 256>>>(X);
    edge_kernel<<<1024, 256>>>(EF, Wgate, bgate, Wscale, bscale,
                               Wshift, bshift, Wbias, bbias, Whead, bhead);
    gemm32_kernel<<<dim3(64, 2), 256, G32_SMEM>>>(0, bq, nullptr);
    r_kernel<<<dim3(32, 8), 256>>>(bk);
    fused_kernel<<<1024, 256, FX_SMEM>>>(X);
    aoh_kernel<<<dim3(32, 8), 256, AO_SMEM>>>(bv);
    gemm32_kernel<<<dim3(64, 2), 256, G32_SMEM>>>(1, bo, out);
}

// round 8
// speedup vs baseline: 16.7480x; 1.3049x over previous
#include <cuda_runtime.h>
#include <cuda_fp16.h>
#include <math.h>

#define BB 1024
#define SS 128
#define DD 256
#define EE 128
#define NHH 8
#define INV_SQRT_HD 0.17677669529663687f
#define RSB 528                 // 264-half pitch (bytes)
#define EGP 272                 // 136-half pitch for K=128 tiles

// ---------------- device scratch ----------------
__device__ __align__(16) __half g_Wt [1024 * 256];  // [WkT|WvT|WqT|WoT] fp16 [n][k]
__device__ __align__(16) __half g_Wkn[256 * 256];   // Wk plain fp16 [k][n]
__device__ __align__(16) __half g_Wet[768 * 128];   // [Wg|Ws|Wh]T fp16 [n][k]
__device__ __align__(16) __half g_EFh[1024 * 128];
__device__ __align__(16) __half g_Qh [2048 * 256];
__device__ __align__(16) __half g_R  [(size_t)BB * 16 * 256];
__device__ __align__(16) __half g_Y  [(size_t)BB * 16 * 256];
__device__ __align__(16) __half g_AO [2048 * 256];
__device__ __align__(16) float  g_pre[(size_t)BB * 768];
__device__ __align__(16) float  g_bkd[BB * 16];
__device__ __align__(16) float  g_a  [BB * DD];
__device__ __align__(16) float  g_s2 [BB * DD];
__device__ __align__(16) float  g_eb [BB * NHH];
__device__ __align__(16) float  g_hs [BB * NHH];

// ---------------- helpers ----------------
__device__ __forceinline__ unsigned smem_u32(const void* p) {
    unsigned a;
    asm("{ .reg .u64 t; cvta.to.shared.u64 t, %1; cvt.u32.u64 %0, t; }" : "=r"(a) : "l"(p));
    return a;
}
__device__ __forceinline__ void ldsm4(unsigned* r, unsigned a) {
    asm volatile("ldmatrix.sync.aligned.m8n8.x4.shared.b16 {%0,%1,%2,%3}, [%4];"
                 : "=r"(r[0]), "=r"(r[1]), "=r"(r[2]), "=r"(r[3]) : "r"(a));
}
__device__ __forceinline__ void ldsm4t(unsigned* r, unsigned a) {
    asm volatile("ldmatrix.sync.aligned.m8n8.x4.trans.shared.b16 {%0,%1,%2,%3}, [%4];"
                 : "=r"(r[0]), "=r"(r[1]), "=r"(r[2]), "=r"(r[3]) : "r"(a));
}
__device__ __forceinline__ void mma16816(float c[4], const unsigned a[4],
                                         unsigned b0, unsigned b1) {
    asm volatile("mma.sync.aligned.m16n8k16.row.col.f32.f16.f16.f32 "
        "{%0,%1,%2,%3}, {%4,%5,%6,%7}, {%8,%9}, {%0,%1,%2,%3};"
        : "+f"(c[0]), "+f"(c[1]), "+f"(c[2]), "+f"(c[3])
        : "r"(a[0]), "r"(a[1]), "r"(a[2]), "r"(a[3]), "r"(b0), "r"(b1));
}

// =====================================================================
// prep conversions
// =====================================================================
__global__ void __launch_bounds__(256)
convert_w_kernel(const float* __restrict__ Wk, const float* __restrict__ Wv,
                 const float* __restrict__ Wq, const float* __restrict__ Wo)
{
    __shared__ float tile[32][33];
    const int n0 = blockIdx.x * 32, k0 = blockIdx.y * 32;
    const float* W = (n0 < 256) ? Wk : (n0 < 512) ? Wv : (n0 < 768) ? Wq : Wo;
    const int ncol = n0 & 255;
    #pragma unroll
    for (int i = 0; i < 4; i++) {
        int k = k0 + threadIdx.y + i * 8;
        tile[threadIdx.y + i * 8][threadIdx.x] = W[k * 256 + ncol + threadIdx.x];
    }
    __syncthreads();
    #pragma unroll
    for (int i = 0; i < 4; i++) {
        int n = n0 + threadIdx.y + i * 8;
        g_Wt[(size_t)n * 256 + k0 + threadIdx.x] =
            __float2half(tile[threadIdx.x][threadIdx.y + i * 8]);
    }
}

__global__ void __launch_bounds__(256)
convert_we_kernel(const float* __restrict__ Wg, const float* __restrict__ Ws,
                  const float* __restrict__ Wh)
{
    __shared__ float tile[32][33];
    const int n0 = blockIdx.x * 32, k0 = blockIdx.y * 32;
    const float* W = (n0 < 256) ? Wg : (n0 < 512) ? Ws : Wh;
    const int ncol = n0 & 255;
    #pragma unroll
    for (int i = 0; i < 4; i++) {
        int k = k0 + threadIdx.y + i * 8;
        tile[threadIdx.y + i * 8][threadIdx.x] = W[k * 256 + ncol + threadIdx.x];
    }
    __syncthreads();
    #pragma unroll
    for (int i = 0; i < 4; i++) {
        int n = n0 + threadIdx.y + i * 8;
        g_Wet[(size_t)n * 128 + k0 + threadIdx.x] =
            __float2half(tile[threadIdx.x][threadIdx.y + i * 8]);
    }
}

__global__ void __launch_bounds__(256)
convert_wkn_kernel(const float* __restrict__ Wk, const float* __restrict__ EF)
{
    int i = blockIdx.x * 256 + threadIdx.x;
    if (i < 32768) {
        float2 v = reinterpret_cast<const float2*>(Wk)[i];
        reinterpret_cast<__half2*>(g_Wkn)[i] = __floats2half2_rn(v.x, v.y);
    }
    int j = i;                  // EF: 65536 half2
    if (j < 65536) {
        float2 v = reinterpret_cast<const float2*>(EF)[j];
        reinterpret_cast<__half2*>(g_EFh)[j] = __floats2half2_rn(v.x, v.y);
    }
}

// =====================================================================
// edge GEMM: g_pre[1024][768] = EFh @ WetT + bias(selected)
//   grid (16, 6): M-tile 64, N-tile 128, K=128.
// =====================================================================
#define EG_B    (64 * EGP)
#define EG_SMEM (64 * EGP + 128 * EGP)

__global__ void __launch_bounds__(256)
gemm_edge_kernel(const float* __restrict__ bg, const float* __restrict__ bs,
                 const float* __restrict__ bh)
{
    extern __shared__ __align__(16) char sm[];
    const unsigned smb = smem_u32(sm);
    const int t = threadIdx.x, w = t >> 5, lane = t & 31;
    const int m0 = blockIdx.x * 64, ny = blockIdx.y;

    #pragma unroll
    for (int i = 0; i < 4; i++) {       // A: 64x128 halves = 1024 uint4
        int idx = t + i * 256;
        int r = idx >> 4, c = idx & 15;
        *reinterpret_cast<uint4*>(sm + (size_t)r * EGP + c * 16) =
            reinterpret_cast<const uint4*>(g_EFh + (size_t)(m0 + r) * 128)[c];
    }
    #pragma unroll
    for (int i = 0; i < 8; i++) {       // B: 128x128 halves = 2048 uint4
        int idx = t + i * 256;
        int r = idx >> 4, c = idx & 15;
        *reinterpret_cast<uint4*>(sm + EG_B + (size_t)r * EGP + c * 16) =
            reinterpret_cast<const uint4*>(g_Wet + (size_t)(ny * 128 + r) * 128)[c];
    }
    __syncthreads();

    const int wm = (w & 1) * 32, wn = (w >> 1) * 32;
    float acc[2][4][4];
    #pragma unroll
    for (int mt = 0; mt < 2; mt++)
        #pragma unroll
        for (int n = 0; n < 4; n++)
            #pragma unroll
            for (int e = 0; e < 4; e++) acc[mt][n][e] = 0.0f;
    const unsigned aA = smb + (unsigned)(wm + (lane & 15)) * EGP + (lane >> 4) * 16;
    const unsigned bA = smb + EG_B + (unsigned)(wn + (lane & 7) + ((lane >> 4) << 3)) * EGP
                        + ((lane >> 3) & 1) * 16;
    #pragma unroll
    for (int ks = 0; ks < 8; ks++) {
        const unsigned ko = ks * 32u;
        unsigned a0[4], a1[4], bb[4];
        ldsm4(a0, aA + ko);
        ldsm4(a1, aA + 16u * EGP + ko);
        #pragma unroll
        for (int g = 0; g < 2; g++) {
            ldsm4(bb, bA + g * (16u * EGP) + ko);
            mma16816(acc[0][2 * g],     a0, bb[0], bb[1]);
            mma16816(acc[0][2 * g + 1], a0, bb[2], bb[3]);
            mma16816(acc[1][2 * g],     a1, bb[0], bb[1]);
            mma16816(acc[1][2 * g + 1], a1, bb[2], bb[3]);
        }
    }
    const float* bp = (ny < 2) ? bg : (ny < 4) ? bs : bh;
    const int boff = (ny & 1) * 128;
    #pragma unroll
    for (int mt = 0; mt < 2; mt++)
        #pragma unroll
        for (int nt = 0; nt < 4; nt++) {
            const int col = wn + nt * 8 + (lane & 3) * 2;
            const int C = ny * 128 + col;
            const int r0 = m0 + wm + mt * 16 + (lane >> 2);
            const float b0 = bp[boff + col], b1 = bp[boff + col + 1];
            *reinterpret_cast<float2*>(&g_pre[(size_t)r0 * 768 + C]) =
                make_float2(acc[mt][nt][0] + b0, acc[mt][nt][1] + b1);
            *reinterpret_cast<float2*>(&g_pre[(size_t)(r0 + 8) * 768 + C]) =
                make_float2(acc[mt][nt][2] + b0, acc[mt][nt][3] + b1);
        }
}

// =====================================================================
// edge combine: activations + eb/hs per batch
// =====================================================================
__global__ void __launch_bounds__(256)
edge_combine_kernel(const float* __restrict__ EF,
                    const float* __restrict__ Wbias, const float* __restrict__ bbias,
                    const float* __restrict__ Whead, const float* __restrict__ bhead)
{
    __shared__ float ef[EE];
    const int b = blockIdx.x, t = threadIdx.x, w = t >> 5, lane = t & 31;
    if (t < EE) ef[t] = EF[(size_t)b * EE + t];
    __syncthreads();

    const float G = g_pre[(size_t)b * 768 + t];
    const float S = g_pre[(size_t)b * 768 + 256 + t];
    const float H = g_pre[(size_t)b * 768 + 512 + t];
    const float gate = 1.0f / (1.0f + expf(-G));
    g_a [b * DD + t] = gate * (1.0f + tanhf(S));
    g_s2[b * DD + t] = gate * H;

    // warp w -> head w: eb and hs via warp reduction
    float ab = 0.0f, ah = 0.0f;
    #pragma unroll
    for (int j = 0; j < 4; j++) {
        const int e = lane + 32 * j;
        const float f = ef[e];
        ab += f * Wbias[e * NHH + w];
        ah += f * Whead[e * NHH + w];
    }
    #pragma unroll
    for (int o = 16; o > 0; o >>= 1) {
        ab += __shfl_xor_sync(0xffffffffu, ab, o);
        ah += __shfl_xor_sync(0xffffffffu, ah, o);
    }
    if (lane == 0) {
        g_eb[b * NHH + w] = bbias[w] + ab;
        g_hs[b * NHH + w] = (1.0f + tanhf(bhead[w] + ah)) * INV_SQRT_HD;
    }
}

// =====================================================================
// gemm32: M-tile 32, N-tile 128.
//   mode0: A = X rows (63,127)/batch (fp32->fp16 inline), W=WqT -> g_Qh fp16.
//   mode1: A = g_AO, W=WoT -> out fp32.
// =====================================================================
#define G32_B    16896u
#define G32_SMEM (16896 + 128 * RSB)

__global__ void __launch_bounds__(256)
gemm32_kernel(int mode, const float* __restrict__ bias, float* __restrict__ outp,
              const float* __restrict__ X)
{
    extern __shared__ __align__(16) char sm[];
    const unsigned smb = smem_u32(sm);
    const int t = threadIdx.x, w = t >> 5, lane = t & 31;
    const int m0 = blockIdx.x * 32, ny = blockIdx.y;
    const __half* Bg = g_Wt + (size_t)((mode ? 768 : 512) + ny * 128) * 256;

    if (mode == 0) {
        #pragma unroll
        for (int i = 0; i < 8; i++) {
            int idx = t + i * 256;              // 2048 float4 (A: 32 rows x 64)
            int r = idx >> 6, c4 = idx & 63;
            const int row = m0 + r, b = row >> 1, s = (row & 1) ? 127 : 63;
            float4 v = reinterpret_cast<const float4*>(X)[((size_t)b * SS + s) * 64 + c4];
            __half2 h0 = __floats2half2_rn(v.x, v.y);
            __half2 h1 = __floats2half2_rn(v.z, v.w);
            uint2 pk;
            pk.x = *reinterpret_cast<unsigned*>(&h0);
            pk.y = *reinterpret_cast<unsigned*>(&h1);
            *reinterpret_cast<uint2*>(sm + (size_t)r * RSB + c4 * 8) = pk;
        }
    } else {
        #pragma unroll
        for (int i = 0; i < 4; i++) {
            int idx = t + i * 256;              // 1024 uint4
            int r = idx >> 5, c = idx & 31;
            *reinterpret_cast<uint4*>(sm + (size_t)r * RSB + c * 16) =
                reinterpret_cast<const uint4*>(g_AO + (size_t)(m0 + r) * 256)[c];
        }
    }
    #pragma unroll
    for (int i = 0; i < 16; i++) {
        int idx = t + i * 256;                  // 4096 uint4 (B: 128x256)
        int r = idx >> 5, c = idx & 31;
        *reinterpret_cast<uint4*>(sm + G32_B + (size_t)r * RSB + c * 16) =
            reinterpret_cast<const uint4*>(Bg + (size_t)r * 256)[c];
    }
    __syncthreads();

    const int wm = (w & 1) * 16, wn = (w >> 1) * 32;
    float acc[4][4];
    #pragma unroll
    for (int n = 0; n < 4; n++)
        #pragma unroll
        for (int e = 0; e < 4; e++) acc[n][e] = 0.0f;
    const unsigned aA = smb + (unsigned)(wm + (lane & 15)) * RSB + (lane >> 4) * 16;
    const unsigned bA = smb + G32_B + (unsigned)(wn + (lane & 7) + ((lane >> 4) << 3)) * RSB
                        + ((lane >> 3) & 1) * 16;
    #pragma unroll
    for (int ks = 0; ks < 16; ks++) {
        const unsigned ko = ks * 32u;
        unsigned a[4], bb[4];
        ldsm4(a, aA + ko);
        #pragma unroll
        for (int g = 0; g < 2; g++) {
            ldsm4(bb, bA + g * (16u * RSB) + ko);
            mma16816(acc[2 * g],     a, bb[0], bb[1]);
            mma16816(acc[2 * g + 1], a, bb[2], bb[3]);
        }
    }
    #pragma unroll
    for (int nt = 0; nt < 4; nt++) {
        const int col = ny * 128 + wn + nt * 8 + (lane & 3) * 2;
        const int r0 = m0 + wm + (lane >> 2);
        const float b0 = bias[col], b1 = bias[col + 1];
        if (mode == 0) {
            *reinterpret_cast<__half2*>(&g_Qh[(size_t)r0 * 256 + col]) =
                __floats2half2_rn(acc[nt][0] + b0, acc[nt][1] + b1);
            *reinterpret_cast<__half2*>(&g_Qh[(size_t)(r0 + 8) * 256 + col]) =
                __floats2half2_rn(acc[nt][2] + b0, acc[nt][3] + b1);
        } else {
            *reinterpret_cast<float2*>(&outp[(size_t)r0 * 256 + col]) =
                make_float2(acc[nt][0] + b0, acc[nt][1] + b1);
            *reinterpret_cast<float2*>(&outp[(size_t)(r0 + 8) * 256 + col]) =
                make_float2(acc[nt][2] + b0, acc[nt][3] + b1);
        }
    }
}

// =====================================================================
// r kernel: R[(b,p)][c] = sum_d Qh[rq][h32+d] * Wk[c][h32+d];  + bkdot.
// =====================================================================
__global__ void __launch_bounds__(256)
r_kernel(const float* __restrict__ bk)
{
    __shared__ __align__(16) __half As[64 * 40];
    __shared__ __align__(16) __half Bs[256 * 40];
    const int t = threadIdx.x, w = t >> 5, lane = t & 31;
    const int m0 = blockIdx.x * 64, h = blockIdx.y;

    {
        int r = t >> 2, c4 = t & 3;
        reinterpret_cast<uint4*>(As + r * 40)[c4] =
            reinterpret_cast<const uint4*>(g_Qh + (size_t)(m0 + r) * 256 + h * 32)[c4];
    }
    #pragma unroll
    for (int i = 0; i < 4; i++) {
        int idx = t + i * 256;
        int r = idx >> 2, c4 = idx & 3;
        reinterpret_cast<uint4*>(Bs + r * 40)[c4] =
            reinterpret_cast<const uint4*>(g_Wkn + (size_t)r * 256 + h * 32)[c4];
    }
    __syncthreads();

    if (t < 64) {
        float s = 0.0f;
        #pragma unroll
        for (int d = 0; d < 32; d++)
            s += __half2float(As[t * 40 + d]) * bk[h * 32 + d];
        g_bkd[(size_t)((m0 + t) >> 1) * 16 + h * 2 + ((m0 + t) & 1)] = s;
    }

    const int wm = (w & 3) * 16, wn = (w >> 2) * 128;
    float acc[16][4];
    #pragma unroll
    for (int n = 0; n < 16; n++)
        #pragma unroll
        for (int e = 0; e < 4; e++) acc[n][e] = 0.0f;
    const unsigned aA = smem_u32(As) + (unsigned)(wm + (lane & 15)) * 80 + (lane >> 4) * 16;
    const unsigned bA = smem_u32(Bs) + (unsigned)(wn + (lane & 7) + ((lane >> 4) << 3)) * 80
                        + ((lane >> 3) & 1) * 16;
    #pragma unroll
    for (int ks = 0; ks < 2; ks++) {
        const unsigned ko = ks * 32u;
        unsigned a[4];
        ldsm4(a, aA + ko);
        #pragma unroll
        for (int g = 0; g < 8; g++) {
            unsigned bb[4];
            ldsm4(bb, bA + g * (16u * 80) + ko);
            mma16816(acc[2 * g],     a, bb[0], bb[1]);
            mma16816(acc[2 * g + 1], a, bb[2], bb[3]);
        }
    }
    #pragma unroll
    for (int nt = 0; nt < 16; nt++) {
        const int c = wn + nt * 8 + (lane & 3) * 2;
        #pragma unroll
        for (int half_ = 0; half_ < 2; half_++) {
            const int rr = m0 + wm + (lane >> 2) + half_ * 8;
            const int bidx = rr >> 1, p = h * 2 + (rr & 1);
            *reinterpret_cast<__half2*>(&g_R[((size_t)bidx * 16 + p) * 256 + c]) =
                __floats2half2_rn(acc[nt][2 * half_], acc[nt][2 * half_ + 1]);
        }
    }
}

// =====================================================================
// FUSED: scores (R @ XhT) + softmax + y (P @ X via ldsm.trans) per batch.
// =====================================================================
#define FX_XH   0
#define FX_R    67584
#define FX_P    (67584 + 8448)
#define FX_S    (76032 + 8704)
#define FX_MISC (84736 + 8192)
#define FX_SMEM (92928 + 128)

__global__ void __launch_bounds__(256, 2)
fused_kernel(const float* __restrict__ X)
{
    extern __shared__ __align__(16) char sm[];
    const unsigned smb = smem_u32(sm);
    float* S   = reinterpret_cast<float*>(sm + FX_S);
    float* msc = reinterpret_cast<float*>(sm + FX_MISC);
    const int t = threadIdx.x, w = t >> 5, lane = t & 31;
    const int b = blockIdx.x;

    if (t < 8)       msc[t] = g_eb[b * NHH + t];
    else if (t < 16) msc[t] = g_hs[b * NHH + (t - 8)];
    else if (t < 32) msc[t] = g_bkd[(size_t)b * 16 + (t - 16)];

    #pragma unroll
    for (int i = 0; i < 2; i++) {
        int idx = t + i * 256;
        int r = idx >> 5, c = idx & 31;
        *reinterpret_cast<uint4*>(sm + FX_R + (size_t)r * RSB + c * 16) =
            reinterpret_cast<const uint4*>(g_R + ((size_t)b * 16 + r) * 256)[c];
    }
    const float4* X4 = reinterpret_cast<const float4*>(X) + (size_t)b * SS * 64;
    #pragma unroll
    for (int i = 0; i < 32; i++) {
        int idx = t + i * 256;
        int r = idx >> 6, kq = idx & 63;
        float4 v = X4[idx];
        __half2 h0 = __floats2half2_rn(v.x, v.y);
        __half2 h1 = __floats2half2_rn(v.z, v.w);
        uint2 pk;
        pk.x = *reinterpret_cast<unsigned*>(&h0);
        pk.y = *reinterpret_cast<unsigned*>(&h1);
        *reinterpret_cast<uint2*>(sm + FX_XH + (size_t)r * RSB + kq * 8) = pk;
    }
    __syncthreads();

    {
        float sa[2][4];
        #pragma unroll
        for (int n = 0; n < 2; n++)
            #pragma unroll
            for (int e = 0; e < 4; e++) sa[n][e] = 0.0f;
        const unsigned aA = smb + FX_R + (unsigned)(lane & 15) * RSB + (lane >> 4) * 16;
        const unsigned bA = smb + FX_XH + (unsigned)(w * 16 + (lane & 7) + ((lane >> 4) << 3)) * RSB
                            + ((lane >> 3) & 1) * 16;
        #pragma unroll
        for (int ks = 0; ks < 16; ks++) {
            const unsigned ko = ks * 32u;
            unsigned a[4], bb[4];
            ldsm4(a, aA + ko);
            ldsm4(bb, bA + ko);
            mma16816(sa[0], a, bb[0], bb[1]);
            mma16816(sa[1], a, bb[2], bb[3]);
        }
        #pragma unroll
        for (int nt = 0; nt < 2; nt++) {
            const int c0 = w * 16 + nt * 8 + (lane & 3) * 2;
            const int p0 = lane >> 2;
            S[p0 * 128 + c0]           = sa[nt][0];
            S[p0 * 128 + c0 + 1]       = sa[nt][1];
            S[(p0 + 8) * 128 + c0]     = sa[nt][2];
            S[(p0 + 8) * 128 + c0 + 1] = sa[nt][3];
        }
    }
    __syncthreads();

    #pragma unroll
    for (int qi = 0; qi < 2; qi++) {
        const int p = w * 2 + qi;
        const int kb = qi ? 63 : 127;
        float sv[4];
        #pragma unroll
        for (int j = 0; j < 4; j++) {
            const int k = lane + 32 * j;
            float s = (S[p * 128 + k] + msc[16 + p]) * msc[8 + w];
            if (k == kb) s += msc[w];
            sv[j] = s;
        }
        float m = fmaxf(fmaxf(sv[0], sv[1]), fmaxf(sv[2], sv[3]));
        #pragma unroll
        for (int o = 16; o > 0; o >>= 1) m = fmaxf(m, __shfl_xor_sync(0xffffffffu, m, o));
        float e[4], sum = 0.0f;
        #pragma unroll
        for (int j = 0; j < 4; j++) { e[j] = expf(sv[j] - m); sum += e[j]; }
        #pragma unroll
        for (int o = 16; o > 0; o >>= 1) sum += __shfl_xor_sync(0xffffffffu, sum, o);
        const float inv = 1.0f / sum;
        #pragma unroll
        for (int j = 0; j < 4; j++) {
            const int k = lane + 32 * j;
            const float pv = e[j] * inv;
            const __half hi = __float2half_rn(pv);
            const __half lo = __float2half_rn(pv - __half2float(hi));
            *reinterpret_cast<__half*>(sm + FX_P + (size_t)p * 272 + k * 2) = hi;
            *reinterpret_cast<__half*>(sm + FX_P + (size_t)(p + 16) * 272 + k * 2) = lo;
        }
    }
    __syncthreads();

    {
        float ya[2][4][4];
        #pragma unroll
        for (int mt = 0; mt < 2; mt++)
            #pragma unroll
            for (int n = 0; n < 4; n++)
                #pragma unroll
                for (int e = 0; e < 4; e++) ya[mt][n][e] = 0.0f;
        const unsigned pA = smb + FX_P + (unsigned)(lane & 15) * 272 + (lane >> 4) * 16;
        const unsigned bT = smb + FX_XH
            + (unsigned)((lane & 7) + ((lane >> 3) & 1) * 8) * RSB
            + (lane >> 4) * 16 + (unsigned)(w * 32) * 2;
        #pragma unroll
        for (int ks = 0; ks < 8; ks++) {
            unsigned a0[4], a1[4], b0[4], b1[4];
            ldsm4(a0, pA + ks * 32u);
            ldsm4(a1, pA + 16u * 272 + ks * 32u);
            ldsm4t(b0, bT + ks * (16u * RSB));
            ldsm4t(b1, bT + 32u + ks * (16u * RSB));
            mma16816(ya[0][0], a0, b0[0], b0[1]);
            mma16816(ya[0][1], a0, b0[2], b0[3]);
            mma16816(ya[0][2], a0, b1[0], b1[1]);
            mma16816(ya[0][3], a0, b1[2], b1[3]);
            mma16816(ya[1][0], a1, b0[0], b0[1]);
            mma16816(ya[1][1], a1, b0[2], b0[3]);
            mma16816(ya[1][2], a1, b1[0], b1[1]);
            mma16816(ya[1][3], a1, b1[2], b1[3]);
        }
        #pragma unroll
        for (int nt = 0; nt < 4; nt++) {
            const int c0 = w * 32 + nt * 8 + (lane & 3) * 2;
            const int p0 = lane >> 2;
            *reinterpret_cast<__half2*>(&g_Y[((size_t)b * 16 + p0) * 256 + c0]) =
                __floats2half2_rn(ya[0][nt][0] + ya[1][nt][0], ya[0][nt][1] + ya[1][nt][1]);
            *reinterpret_cast<__half2*>(&g_Y[((size_t)b * 16 + p0 + 8) * 256 + c0]) =
                __floats2half2_rn(ya[0][nt][2] + ya[1][nt][2], ya[0][nt][3] + ya[1][nt][3]);
        }
    }
}

// =====================================================================
// AOh: per-head GEMM with gating epilogue
// =====================================================================
#define AO_B    33792u
#define AO_SMEM (33792 + 32 * RSB)

__global__ void __launch_bounds__(256)
aoh_kernel(const float* __restrict__ bv)
{
    extern __shared__ __align__(16) char sm[];
    const unsigned smb = smem_u32(sm);
    const int t = threadIdx.x, w = t >> 5, lane = t & 31;
    const int b0 = blockIdx.x * 32, h = blockIdx.y;

    #pragma unroll
    for (int i = 0; i < 8; i++) {
        int idx = t + i * 256;
        int rr = idx >> 5, c = idx & 31;
        const size_t src = ((size_t)(b0 + (rr >> 1)) * 16 + h * 2 + (rr & 1)) * 256;
        *reinterpret_cast<uint4*>(sm + (size_t)rr * RSB + c * 16) =
            reinterpret_cast<const uint4*>(g_Y + src)[c];
    }
    #pragma unroll
    for (int i = 0; i < 4; i++) {
        int idx = t + i * 256;
        int r = idx >> 5, c = idx & 31;
        *reinterpret_cast<uint4*>(sm + AO_B + (size_t)r * RSB + c * 16) =
            reinterpret_cast<const uint4*>(g_Wt + (size_t)(256 + h * 32 + r) * 256)[c];
    }
    __syncthreads();

    const int wm = (w & 3) * 16, wn = (w >> 2) * 16;
    float acc[2][4];
    #pragma unroll
    for (int n = 0; n < 2; n++)
        #pragma unroll
        for (int e = 0; e < 4; e++) acc[n][e] = 0.0f;
    const unsigned aA = smb + (unsigned)(wm + (lane & 15)) * RSB + (lane >> 4) * 16;
    const unsigned bA = smb + AO_B + (unsigned)(wn + (lane & 7) + ((lane >> 4) << 3)) * RSB
                        + ((lane >> 3) & 1) * 16;
    #pragma unroll
    for (int ks = 0; ks < 16; ks++) {
        const unsigned ko = ks * 32u;
        unsigned a[4], bb[4];
        ldsm4(a, aA + ko);
        ldsm4(bb, bA + ko);
        mma16816(acc[0], a, bb[0], bb[1]);
        mma16816(acc[1], a, bb[2], bb[3]);
    }
    #pragma unroll
    for (int nt = 0; nt < 2; nt++) {
        const int col = wn + nt * 8 + (lane & 3) * 2;
        const int C = h * 32 + col;
        const float b0f = bv[C], b1f = bv[C + 1];
        #pragma unroll
        for (int half_ = 0; half_ < 2; half_++) {
            const int rr = wm + (lane >> 2) + half_ * 8;
            const int bb_ = b0 + (rr >> 1), qi = rr & 1;
            const float a0 = g_a[bb_ * DD + C],  a1 = g_a[bb_ * DD + C + 1];
            const float s0 = g_s2[bb_ * DD + C], s1 = g_s2[bb_ * DD + C + 1];
            *reinterpret_cast<__half2*>(&g_AO[(size_t)(bb_ * 2 + qi) * 256 + C]) =
                __floats2half2_rn((acc[nt][2 * half_]     + b0f) * a0 + s0,
                                  (acc[nt][2 * half_ + 1] + b1f) * a1 + s1);
        }
    }
}

// =====================================================================
extern "C" void kernel_launch(void* const* d_in, const int* in_sizes, int n_in,
                              void* d_out, int out_size)
{
    (void)in_sizes; (void)n_in; (void)out_size;
    const float* X      = (const float*)d_in[0];
    const float* EF     = (const float*)d_in[1];
    const float* Wq     = (const float*)d_in[2];
    const float* bq     = (const float*)d_in[3];
    const float* Wk     = (const float*)d_in[4];
    const float* bk     = (const float*)d_in[5];
    const float* Wv     = (const float*)d_in[6];
    const float* bv     = (const float*)d_in[7];
    const float* Wo     = (const float*)d_in[8];
    const float* bo     = (const float*)d_in[9];
    const float* Wbias  = (const float*)d_in[10];
    const float* bbias  = (const float*)d_in[11];
    const float* Wgate  = (const float*)d_in[12];
    const float* bgate  = (const float*)d_in[13];
    const float* Wscale = (const float*)d_in[14];
    const float* bscale = (const float*)d_in[15];
    const float* Wshift = (const float*)d_in[16];
    const float* bshift = (const float*)d_in[17];
    const float* Whead  = (const float*)d_in[18];
    const float* bhead  = (const float*)d_in[19];
    float* out = (float*)d_out;

    cudaFuncSetAttribute(gemm_edge_kernel, cudaFuncAttributeMaxDynamicSharedMemorySize, EG_SMEM);
    cudaFuncSetAttribute(gemm32_kernel, cudaFuncAttributeMaxDynamicSharedMemorySize, G32_SMEM);
    cudaFuncSetAttribute(fused_kernel,  cudaFuncAttributeMaxDynamicSharedMemorySize, FX_SMEM);
    cudaFuncSetAttribute(aoh_kernel,    cudaFuncAttributeMaxDynamicSharedMemorySize, AO_SMEM);

    convert_w_kernel<<<dim3(32, 8), dim3(32, 8)>>>(Wk, Wv, Wq, Wo);
    convert_we_kernel<<<dim3(24, 4), dim3(32, 8)>>>(Wgate, Wscale, Wshift);
    convert_wkn_kernel<<<256, 256>>>(Wk, EF);
    gemm_edge_kernel<<<dim3(16, 6), 256, EG_SMEM>>>(bgate, bscale, bshift);
    edge_combine_kernel<<<1024, 256>>>(EF, Wbias, bbias, Whead, bhead);
    gemm32_kernel<<<dim3(64, 2), 256, G32_SMEM>>>(0, bq, nullptr, X);
    r_kernel<<<dim3(32, 8), 256>>>(bk);
    fused_kernel<<<1024, 256, FX_SMEM>>>(X);
    aoh_kernel<<<dim3(32, 8), 256, AO_SMEM>>>(bv);
    gemm32_kernel<<<dim3(64, 2), 256, G32_SMEM>>>(1, bo, out, X);
}

// round 9
// speedup vs baseline: 18.2521x; 1.0898x over previous
#include <cuda_runtime.h>
#include <cuda_fp16.h>
#include <math.h>

#define BB 1024
#define SS 128
#define DD 256
#define EE 128
#define NHH 8
#define INV_SQRT_HD 0.17677669529663687f
#define RSB 528                 // 264-half pitch (bytes)
#define EGP 272                 // 136-half pitch (bytes)

// ---------------- device scratch ----------------
__device__ __align__(16) __half g_Wt [1024 * 256];  // [WkT|WvT|WqT|WoT] fp16 [n][k]
__device__ __align__(16) __half g_Wkn[256 * 256];   // Wk plain fp16 [k][n]
__device__ __align__(16) __half g_Wet[768 * 128];   // [Wg|Ws|Wh]T fp16 [n][k]
__device__ __align__(16) __half g_EFh[1024 * 128];
__device__ __align__(16) __half g_Qh [2048 * 256];
__device__ __align__(16) __half g_R  [(size_t)BB * 16 * 256];
__device__ __align__(16) __half g_Y  [(size_t)BB * 16 * 256];
__device__ __align__(16) __half g_AO [2048 * 256];
__device__ __align__(16) float  g_pre[(size_t)BB * 768];
__device__ __align__(16) float  g_bkd[BB * 16];
__device__ __align__(16) float  g_a  [BB * DD];
__device__ __align__(16) float  g_s2 [BB * DD];
__device__ __align__(16) float  g_eb [BB * NHH];
__device__ __align__(16) float  g_hs [BB * NHH];

// ---------------- helpers ----------------
__device__ __forceinline__ unsigned smem_u32(const void* p) {
    unsigned a;
    asm("{ .reg .u64 t; cvta.to.shared.u64 t, %1; cvt.u32.u64 %0, t; }" : "=r"(a) : "l"(p));
    return a;
}
__device__ __forceinline__ void ldsm4(unsigned* r, unsigned a) {
    asm volatile("ldmatrix.sync.aligned.m8n8.x4.shared.b16 {%0,%1,%2,%3}, [%4];"
                 : "=r"(r[0]), "=r"(r[1]), "=r"(r[2]), "=r"(r[3]) : "r"(a));
}
__device__ __forceinline__ void ldsm4t(unsigned* r, unsigned a) {
    asm volatile("ldmatrix.sync.aligned.m8n8.x4.trans.shared.b16 {%0,%1,%2,%3}, [%4];"
                 : "=r"(r[0]), "=r"(r[1]), "=r"(r[2]), "=r"(r[3]) : "r"(a));
}
__device__ __forceinline__ void mma16816(float c[4], const unsigned a[4],
                                         unsigned b0, unsigned b1) {
    asm volatile("mma.sync.aligned.m16n8k16.row.col.f32.f16.f16.f32 "
        "{%0,%1,%2,%3}, {%4,%5,%6,%7}, {%8,%9}, {%0,%1,%2,%3};"
        : "+f"(c[0]), "+f"(c[1]), "+f"(c[2]), "+f"(c[3])
        : "r"(a[0]), "r"(a[1]), "r"(a[2]), "r"(a[3]), "r"(b0), "r"(b1));
}

// =====================================================================
// prep: all weight/EF conversions in one launch (608 CTAs)
// =====================================================================
__global__ void __launch_bounds__(256)
prep_kernel(const float* __restrict__ Wk, const float* __restrict__ Wv,
            const float* __restrict__ Wq, const float* __restrict__ Wo,
            const float* __restrict__ Wg, const float* __restrict__ Ws,
            const float* __restrict__ Wh, const float* __restrict__ EF)
{
    __shared__ float tile[32][33];
    const int bid = blockIdx.x, t = threadIdx.x;
    const int tx = t & 31, ty = t >> 5;

    if (bid < 256) {            // convert [Wk|Wv|Wq|Wo] -> g_Wt
        const int n0 = (bid & 31) * 32, k0 = (bid >> 5) * 32;
        const float* W = (n0 < 256) ? Wk : (n0 < 512) ? Wv : (n0 < 768) ? Wq : Wo;
        const int ncol = n0 & 255;
        #pragma unroll
        for (int i = 0; i < 4; i++) {
            int k = k0 + ty + i * 8;
            tile[ty + i * 8][tx] = W[k * 256 + ncol + tx];
        }
        __syncthreads();
        #pragma unroll
        for (int i = 0; i < 4; i++) {
            int n = n0 + ty + i * 8;
            g_Wt[(size_t)n * 256 + k0 + tx] = __float2half(tile[tx][ty + i * 8]);
        }
    } else if (bid < 352) {     // convert [Wg|Ws|Wh] -> g_Wet
        const int idx = bid - 256;
        const int n0 = (idx % 24) * 32, k0 = (idx / 24) * 32;
        const float* W = (n0 < 256) ? Wg : (n0 < 512) ? Ws : Wh;
        const int ncol = n0 & 255;
        #pragma unroll
        for (int i = 0; i < 4; i++) {
            int k = k0 + ty + i * 8;
            tile[ty + i * 8][tx] = W[k * 256 + ncol + tx];
        }
        __syncthreads();
        #pragma unroll
        for (int i = 0; i < 4; i++) {
            int n = n0 + ty + i * 8;
            g_Wet[(size_t)n * 128 + k0 + tx] = __float2half(tile[tx][ty + i * 8]);
        }
    } else {                    // Wkn + EF fp16
        const int i = (bid - 352) * 256 + t;
        if (i < 32768) {
            float2 v = reinterpret_cast<const float2*>(Wk)[i];
            reinterpret_cast<__half2*>(g_Wkn)[i] = __floats2half2_rn(v.x, v.y);
        }
        float2 v = reinterpret_cast<const float2*>(EF)[i];
        reinterpret_cast<__half2*>(g_EFh)[i] = __floats2half2_rn(v.x, v.y);
    }
}

// =====================================================================
// gemm32 body (shared by mid1 mode0 and final mode1)
// =====================================================================
#define G32_B    16896u
#define G32_SMEM (16896 + 128 * RSB)

__device__ __forceinline__ void gemm32_body(
    int mode, const float* __restrict__ bias, float* __restrict__ outp,
    const float* __restrict__ X, int m0, int ny, char* sm, unsigned smb)
{
    const int t = threadIdx.x, w = t >> 5, lane = t & 31;
    const __half* Bg = g_Wt + (size_t)((mode ? 768 : 512) + ny * 128) * 256;

    if (mode == 0) {
        #pragma unroll
        for (int i = 0; i < 8; i++) {
            int idx = t + i * 256;
            int r = idx >> 6, c4 = idx & 63;
            const int row = m0 + r, b = row >> 1, s = (row & 1) ? 127 : 63;
            float4 v = reinterpret_cast<const float4*>(X)[((size_t)b * SS + s) * 64 + c4];
            __half2 h0 = __floats2half2_rn(v.x, v.y);
            __half2 h1 = __floats2half2_rn(v.z, v.w);
            uint2 pk;
            pk.x = *reinterpret_cast<unsigned*>(&h0);
            pk.y = *reinterpret_cast<unsigned*>(&h1);
            *reinterpret_cast<uint2*>(sm + (size_t)r * RSB + c4 * 8) = pk;
        }
    } else {
        #pragma unroll
        for (int i = 0; i < 4; i++) {
            int idx = t + i * 256;
            int r = idx >> 5, c = idx & 31;
            *reinterpret_cast<uint4*>(sm + (size_t)r * RSB + c * 16) =
                reinterpret_cast<const uint4*>(g_AO + (size_t)(m0 + r) * 256)[c];
        }
    }
    #pragma unroll
    for (int i = 0; i < 16; i++) {
        int idx = t + i * 256;
        int r = idx >> 5, c = idx & 31;
        *reinterpret_cast<uint4*>(sm + G32_B + (size_t)r * RSB + c * 16) =
            reinterpret_cast<const uint4*>(Bg + (size_t)r * 256)[c];
    }
    __syncthreads();

    const int wm = (w & 1) * 16, wn = (w >> 1) * 32;
    float acc[4][4];
    #pragma unroll
    for (int n = 0; n < 4; n++)
        #pragma unroll
        for (int e = 0; e < 4; e++) acc[n][e] = 0.0f;
    const unsigned aA = smb + (unsigned)(wm + (lane & 15)) * RSB + (lane >> 4) * 16;
    const unsigned bA = smb + G32_B + (unsigned)(wn + (lane & 7) + ((lane >> 4) << 3)) * RSB
                        + ((lane >> 3) & 1) * 16;
    #pragma unroll
    for (int ks = 0; ks < 16; ks++) {
        const unsigned ko = ks * 32u;
        unsigned a[4], bb[4];
        ldsm4(a, aA + ko);
        #pragma unroll
        for (int g = 0; g < 2; g++) {
            ldsm4(bb, bA + g * (16u * RSB) + ko);
            mma16816(acc[2 * g],     a, bb[0], bb[1]);
            mma16816(acc[2 * g + 1], a, bb[2], bb[3]);
        }
    }
    #pragma unroll
    for (int nt = 0; nt < 4; nt++) {
        const int col = ny * 128 + wn + nt * 8 + (lane & 3) * 2;
        const int r0 = m0 + wm + (lane >> 2);
        const float b0 = bias[col], b1 = bias[col + 1];
        if (mode == 0) {
            *reinterpret_cast<__half2*>(&g_Qh[(size_t)r0 * 256 + col]) =
                __floats2half2_rn(acc[nt][0] + b0, acc[nt][1] + b1);
            *reinterpret_cast<__half2*>(&g_Qh[(size_t)(r0 + 8) * 256 + col]) =
                __floats2half2_rn(acc[nt][2] + b0, acc[nt][3] + b1);
        } else {
            *reinterpret_cast<float2*>(&outp[(size_t)r0 * 256 + col]) =
                make_float2(acc[nt][0] + b0, acc[nt][1] + b1);
            *reinterpret_cast<float2*>(&outp[(size_t)(r0 + 8) * 256 + col]) =
                make_float2(acc[nt][2] + b0, acc[nt][3] + b1);
        }
    }
}

// =====================================================================
// mid1: edge GEMM (CTAs 0..95) + Q projection (CTAs 96..223)
// =====================================================================
#define EG_B (64 * EGP)

__global__ void __launch_bounds__(256)
mid1_kernel(const float* __restrict__ bg, const float* __restrict__ bs,
            const float* __restrict__ bh, const float* __restrict__ bq,
            const float* __restrict__ X)
{
    extern __shared__ __align__(16) char sm[];
    const unsigned smb = smem_u32(sm);
    const int bid = blockIdx.x, t = threadIdx.x, w = t >> 5, lane = t & 31;

    if (bid >= 96) {            // Q projection (gemm32 mode 0)
        const int idx = bid - 96;
        gemm32_body(0, bq, nullptr, X, (idx & 63) * 32, idx >> 6, sm, smb);
        return;
    }
    // ---- edge GEMM: g_pre = EFh @ WetT + bias ----
    const int m0 = (bid % 16) * 64, ny = bid / 16;
    #pragma unroll
    for (int i = 0; i < 4; i++) {
        int idx = t + i * 256;
        int r = idx >> 4, c = idx & 15;
        *reinterpret_cast<uint4*>(sm + (size_t)r * EGP + c * 16) =
            reinterpret_cast<const uint4*>(g_EFh + (size_t)(m0 + r) * 128)[c];
    }
    #pragma unroll
    for (int i = 0; i < 8; i++) {
        int idx = t + i * 256;
        int r = idx >> 4, c = idx & 15;
        *reinterpret_cast<uint4*>(sm + EG_B + (size_t)r * EGP + c * 16) =
            reinterpret_cast<const uint4*>(g_Wet + (size_t)(ny * 128 + r) * 128)[c];
    }
    __syncthreads();

    const int wm = (w & 1) * 32, wn = (w >> 1) * 32;
    float acc[2][4][4];
    #pragma unroll
    for (int mt = 0; mt < 2; mt++)
        #pragma unroll
        for (int n = 0; n < 4; n++)
            #pragma unroll
            for (int e = 0; e < 4; e++) acc[mt][n][e] = 0.0f;
    const unsigned aA = smb + (unsigned)(wm + (lane & 15)) * EGP + (lane >> 4) * 16;
    const unsigned bA = smb + EG_B + (unsigned)(wn + (lane & 7) + ((lane >> 4) << 3)) * EGP
                        + ((lane >> 3) & 1) * 16;
    #pragma unroll
    for (int ks = 0; ks < 8; ks++) {
        const unsigned ko = ks * 32u;
        unsigned a0[4], a1[4], bb[4];
        ldsm4(a0, aA + ko);
        ldsm4(a1, aA + 16u * EGP + ko);
        #pragma unroll
        for (int g = 0; g < 2; g++) {
            ldsm4(bb, bA + g * (16u * EGP) + ko);
            mma16816(acc[0][2 * g],     a0, bb[0], bb[1]);
            mma16816(acc[0][2 * g + 1], a0, bb[2], bb[3]);
            mma16816(acc[1][2 * g],     a1, bb[0], bb[1]);
            mma16816(acc[1][2 * g + 1], a1, bb[2], bb[3]);
        }
    }
    const float* bp = (ny < 2) ? bg : (ny < 4) ? bs : bh;
    const int boff = (ny & 1) * 128;
    #pragma unroll
    for (int mt = 0; mt < 2; mt++)
        #pragma unroll
        for (int nt = 0; nt < 4; nt++) {
            const int col = wn + nt * 8 + (lane & 3) * 2;
            const int C = ny * 128 + col;
            const int r0 = m0 + wm + mt * 16 + (lane >> 2);
            const float b0 = bp[boff + col], b1 = bp[boff + col + 1];
            *reinterpret_cast<float2*>(&g_pre[(size_t)r0 * 768 + C]) =
                make_float2(acc[mt][nt][0] + b0, acc[mt][nt][1] + b1);
            *reinterpret_cast<float2*>(&g_pre[(size_t)(r0 + 8) * 768 + C]) =
                make_float2(acc[mt][nt][2] + b0, acc[mt][nt][3] + b1);
        }
}

// =====================================================================
// mid2: r kernel (CTAs 0..255) + edge combine (CTAs 256..1279)
// =====================================================================
__global__ void __launch_bounds__(256)
mid2_kernel(const float* __restrict__ EF,
            const float* __restrict__ Wbias, const float* __restrict__ bbias,
            const float* __restrict__ Whead, const float* __restrict__ bhead,
            const float* __restrict__ bk)
{
    __shared__ __align__(16) __half As[64 * 40];
    __shared__ __align__(16) __half Bs[256 * 40];
    __shared__ float ef[EE];
    const int bid = blockIdx.x, t = threadIdx.x, w = t >> 5, lane = t & 31;

    if (bid >= 256) {
        // ---- edge combine ----
        const int b = bid - 256;
        if (t < EE) ef[t] = EF[(size_t)b * EE + t];
        __syncthreads();
        const float G = g_pre[(size_t)b * 768 + t];
        const float S = g_pre[(size_t)b * 768 + 256 + t];
        const float H = g_pre[(size_t)b * 768 + 512 + t];
        const float gate = 1.0f / (1.0f + expf(-G));
        g_a [b * DD + t] = gate * (1.0f + tanhf(S));
        g_s2[b * DD + t] = gate * H;

        float ab = 0.0f, ah = 0.0f;
        #pragma unroll
        for (int j = 0; j < 4; j++) {
            const int e = lane + 32 * j;
            const float f = ef[e];
            ab += f * Wbias[e * NHH + w];
            ah += f * Whead[e * NHH + w];
        }
        #pragma unroll
        for (int o = 16; o > 0; o >>= 1) {
            ab += __shfl_xor_sync(0xffffffffu, ab, o);
            ah += __shfl_xor_sync(0xffffffffu, ah, o);
        }
        if (lane == 0) {
            g_eb[b * NHH + w] = bbias[w] + ab;
            g_hs[b * NHH + w] = (1.0f + tanhf(bhead[w] + ah)) * INV_SQRT_HD;
        }
        return;
    }
    // ---- r kernel ----
    const int m0 = (bid & 31) * 64, h = bid >> 5;
    {
        int r = t >> 2, c4 = t & 3;
        reinterpret_cast<uint4*>(As + r * 40)[c4] =
            reinterpret_cast<const uint4*>(g_Qh + (size_t)(m0 + r) * 256 + h * 32)[c4];
    }
    #pragma unroll
    for (int i = 0; i < 4; i++) {
        int idx = t + i * 256;
        int r = idx >> 2, c4 = idx & 3;
        reinterpret_cast<uint4*>(Bs + r * 40)[c4] =
            reinterpret_cast<const uint4*>(g_Wkn + (size_t)r * 256 + h * 32)[c4];
    }
    __syncthreads();

    if (t < 64) {
        float s = 0.0f;
        #pragma unroll
        for (int d = 0; d < 32; d++)
            s += __half2float(As[t * 40 + d]) * bk[h * 32 + d];
        g_bkd[(size_t)((m0 + t) >> 1) * 16 + h * 2 + ((m0 + t) & 1)] = s;
    }

    const int wm = (w & 3) * 16, wn = (w >> 2) * 128;
    float acc[16][4];
    #pragma unroll
    for (int n = 0; n < 16; n++)
        #pragma unroll
        for (int e = 0; e < 4; e++) acc[n][e] = 0.0f;
    const unsigned aA = smem_u32(As) + (unsigned)(wm + (lane & 15)) * 80 + (lane >> 4) * 16;
    const unsigned bA = smem_u32(Bs) + (unsigned)(wn + (lane & 7) + ((lane >> 4) << 3)) * 80
                        + ((lane >> 3) & 1) * 16;
    #pragma unroll
    for (int ks = 0; ks < 2; ks++) {
        const unsigned ko = ks * 32u;
        unsigned a[4];
        ldsm4(a, aA + ko);
        #pragma unroll
        for (int g = 0; g < 8; g++) {
            unsigned bb[4];
            ldsm4(bb, bA + g * (16u * 80) + ko);
            mma16816(acc[2 * g],     a, bb[0], bb[1]);
            mma16816(acc[2 * g + 1], a, bb[2], bb[3]);
        }
    }
    #pragma unroll
    for (int nt = 0; nt < 16; nt++) {
        const int c = wn + nt * 8 + (lane & 3) * 2;
        #pragma unroll
        for (int half_ = 0; half_ < 2; half_++) {
            const int rr = m0 + wm + (lane >> 2) + half_ * 8;
            const int bidx = rr >> 1, p = h * 2 + (rr & 1);
            *reinterpret_cast<__half2*>(&g_R[((size_t)bidx * 16 + p) * 256 + c]) =
                __floats2half2_rn(acc[nt][2 * half_], acc[nt][2 * half_ + 1]);
        }
    }
}

// =====================================================================
// FUSED: scores (R @ XhT) + softmax + y (P @ X via ldsm.trans) per batch.
// =====================================================================
#define FX_XH   0
#define FX_R    67584
#define FX_P    (67584 + 8448)
#define FX_S    (76032 + 8704)
#define FX_MISC (84736 + 8192)
#define FX_SMEM (92928 + 128)

__global__ void __launch_bounds__(256, 2)
fused_kernel(const float* __restrict__ X)
{
    extern __shared__ __align__(16) char sm[];
    const unsigned smb = smem_u32(sm);
    float* S   = reinterpret_cast<float*>(sm + FX_S);
    float* msc = reinterpret_cast<float*>(sm + FX_MISC);
    const int t = threadIdx.x, w = t >> 5, lane = t & 31;
    const int b = blockIdx.x;

    if (t < 8)       msc[t] = g_eb[b * NHH + t];
    else if (t < 16) msc[t] = g_hs[b * NHH + (t - 8)];
    else if (t < 32) msc[t] = g_bkd[(size_t)b * 16 + (t - 16)];

    #pragma unroll
    for (int i = 0; i < 2; i++) {
        int idx = t + i * 256;
        int r = idx >> 5, c = idx & 31;
        *reinterpret_cast<uint4*>(sm + FX_R + (size_t)r * RSB + c * 16) =
            reinterpret_cast<const uint4*>(g_R + ((size_t)b * 16 + r) * 256)[c];
    }
    const float4* X4 = reinterpret_cast<const float4*>(X) + (size_t)b * SS * 64;
    #pragma unroll
    for (int i = 0; i < 32; i++) {
        int idx = t + i * 256;
        int r = idx >> 6, kq = idx & 63;
        float4 v = X4[idx];
        __half2 h0 = __floats2half2_rn(v.x, v.y);
        __half2 h1 = __floats2half2_rn(v.z, v.w);
        uint2 pk;
        pk.x = *reinterpret_cast<unsigned*>(&h0);
        pk.y = *reinterpret_cast<unsigned*>(&h1);
        *reinterpret_cast<uint2*>(sm + FX_XH + (size_t)r * RSB + kq * 8) = pk;
    }
    __syncthreads();

    {
        float sa[2][4];
        #pragma unroll
        for (int n = 0; n < 2; n++)
            #pragma unroll
            for (int e = 0; e < 4; e++) sa[n][e] = 0.0f;
        const unsigned aA = smb + FX_R + (unsigned)(lane & 15) * RSB + (lane >> 4) * 16;
        const unsigned bA = smb + FX_XH + (unsigned)(w * 16 + (lane & 7) + ((lane >> 4) << 3)) * RSB
                            + ((lane >> 3) & 1) * 16;
        #pragma unroll
        for (int ks = 0; ks < 16; ks++) {
            const unsigned ko = ks * 32u;
            unsigned a[4], bb[4];
            ldsm4(a, aA + ko);
            ldsm4(bb, bA + ko);
            mma16816(sa[0], a, bb[0], bb[1]);
            mma16816(sa[1], a, bb[2], bb[3]);
        }
        #pragma unroll
        for (int nt = 0; nt < 2; nt++) {
            const int c0 = w * 16 + nt * 8 + (lane & 3) * 2;
            const int p0 = lane >> 2;
            S[p0 * 128 + c0]           = sa[nt][0];
            S[p0 * 128 + c0 + 1]       = sa[nt][1];
            S[(p0 + 8) * 128 + c0]     = sa[nt][2];
            S[(p0 + 8) * 128 + c0 + 1] = sa[nt][3];
        }
    }
    __syncthreads();

    #pragma unroll
    for (int qi = 0; qi < 2; qi++) {
        const int p = w * 2 + qi;
        const int kb = qi ? 63 : 127;
        float sv[4];
        #pragma unroll
        for (int j = 0; j < 4; j++) {
            const int k = lane + 32 * j;
            float s = (S[p * 128 + k] + msc[16 + p]) * msc[8 + w];
            if (k == kb) s += msc[w];
            sv[j] = s;
        }
        float m = fmaxf(fmaxf(sv[0], sv[1]), fmaxf(sv[2], sv[3]));
        #pragma unroll
        for (int o = 16; o > 0; o >>= 1) m = fmaxf(m, __shfl_xor_sync(0xffffffffu, m, o));
        float e[4], sum = 0.0f;
        #pragma unroll
        for (int j = 0; j < 4; j++) { e[j] = expf(sv[j] - m); sum += e[j]; }
        #pragma unroll
        for (int o = 16; o > 0; o >>= 1) sum += __shfl_xor_sync(0xffffffffu, sum, o);
        const float inv = 1.0f / sum;
        #pragma unroll
        for (int j = 0; j < 4; j++) {
            const int k = lane + 32 * j;
            const float pv = e[j] * inv;
            const __half hi = __float2half_rn(pv);
            const __half lo = __float2half_rn(pv - __half2float(hi));
            *reinterpret_cast<__half*>(sm + FX_P + (size_t)p * 272 + k * 2) = hi;
            *reinterpret_cast<__half*>(sm + FX_P + (size_t)(p + 16) * 272 + k * 2) = lo;
        }
    }
    __syncthreads();

    {
        float ya[2][4][4];
        #pragma unroll
        for (int mt = 0; mt < 2; mt++)
            #pragma unroll
            for (int n = 0; n < 4; n++)
                #pragma unroll
                for (int e = 0; e < 4; e++) ya[mt][n][e] = 0.0f;
        const unsigned pA = smb + FX_P + (unsigned)(lane & 15) * 272 + (lane >> 4) * 16;
        const unsigned bT = smb + FX_XH
            + (unsigned)((lane & 7) + ((lane >> 3) & 1) * 8) * RSB
            + (lane >> 4) * 16 + (unsigned)(w * 32) * 2;
        #pragma unroll
        for (int ks = 0; ks < 8; ks++) {
            unsigned a0[4], a1[4], b0[4], b1[4];
            ldsm4(a0, pA + ks * 32u);
            ldsm4(a1, pA + 16u * 272 + ks * 32u);
            ldsm4t(b0, bT + ks * (16u * RSB));
            ldsm4t(b1, bT + 32u + ks * (16u * RSB));
            mma16816(ya[0][0], a0, b0[0], b0[1]);
            mma16816(ya[0][1], a0, b0[2], b0[3]);
            mma16816(ya[0][2], a0, b1[0], b1[1]);
            mma16816(ya[0][3], a0, b1[2], b1[3]);
            mma16816(ya[1][0], a1, b0[0], b0[1]);
            mma16816(ya[1][1], a1, b0[2], b0[3]);
            mma16816(ya[1][2], a1, b1[0], b1[1]);
            mma16816(ya[1][3], a1, b1[2], b1[3]);
        }
        #pragma unroll
        for (int nt = 0; nt < 4; nt++) {
            const int c0 = w * 32 + nt * 8 + (lane & 3) * 2;
            const int p0 = lane >> 2;
            *reinterpret_cast<__half2*>(&g_Y[((size_t)b * 16 + p0) * 256 + c0]) =
                __floats2half2_rn(ya[0][nt][0] + ya[1][nt][0], ya[0][nt][1] + ya[1][nt][1]);
            *reinterpret_cast<__half2*>(&g_Y[((size_t)b * 16 + p0 + 8) * 256 + c0]) =
                __floats2half2_rn(ya[0][nt][2] + ya[1][nt][2], ya[0][nt][3] + ya[1][nt][3]);
        }
    }
}

// =====================================================================
// AOh: per-head GEMM with gating epilogue
// =====================================================================
#define AO_B    33792u
#define AO_SMEM (33792 + 32 * RSB)

__global__ void __launch_bounds__(256)
aoh_kernel(const float* __restrict__ bv)
{
    extern __shared__ __align__(16) char sm[];
    const unsigned smb = smem_u32(sm);
    const int t = threadIdx.x, w = t >> 5, lane = t & 31;
    const int b0 = (blockIdx.x & 31) * 32, h = blockIdx.x >> 5;

    #pragma unroll
    for (int i = 0; i < 8; i++) {
        int idx = t + i * 256;
        int rr = idx >> 5, c = idx & 31;
        const size_t src = ((size_t)(b0 + (rr >> 1)) * 16 + h * 2 + (rr & 1)) * 256;
        *reinterpret_cast<uint4*>(sm + (size_t)rr * RSB + c * 16) =
            reinterpret_cast<const uint4*>(g_Y + src)[c];
    }
    #pragma unroll
    for (int i = 0; i < 4; i++) {
        int idx = t + i * 256;
        int r = idx >> 5, c = idx & 31;
        *reinterpret_cast<uint4*>(sm + AO_B + (size_t)r * RSB + c * 16) =
            reinterpret_cast<const uint4*>(g_Wt + (size_t)(256 + h * 32 + r) * 256)[c];
    }
    __syncthreads();

    const int wm = (w & 3) * 16, wn = (w >> 2) * 16;
    float acc[2][4];
    #pragma unroll
    for (int n = 0; n < 2; n++)
        #pragma unroll
        for (int e = 0; e < 4; e++) acc[n][e] = 0.0f;
    const unsigned aA = smb + (unsigned)(wm + (lane & 15)) * RSB + (lane >> 4) * 16;
    const unsigned bA = smb + AO_B + (unsigned)(wn + (lane & 7) + ((lane >> 4) << 3)) * RSB
                        + ((lane >> 3) & 1) * 16;
    #pragma unroll
    for (int ks = 0; ks < 16; ks++) {
        const unsigned ko = ks * 32u;
        unsigned a[4], bb[4];
        ldsm4(a, aA + ko);
        ldsm4(bb, bA + ko);
        mma16816(acc[0], a, bb[0], bb[1]);
        mma16816(acc[1], a, bb[2], bb[3]);
    }
    #pragma unroll
    for (int nt = 0; nt < 2; nt++) {
        const int col = wn + nt * 8 + (lane & 3) * 2;
        const int C = h * 32 + col;
        const float b0f = bv[C], b1f = bv[C + 1];
        #pragma unroll
        for (int half_ = 0; half_ < 2; half_++) {
            const int rr = wm + (lane >> 2) + half_ * 8;
            const int bb_ = b0 + (rr >> 1), qi = rr & 1;
            const float a0 = g_a[bb_ * DD + C],  a1 = g_a[bb_ * DD + C + 1];
            const float s0 = g_s2[bb_ * DD + C], s1 = g_s2[bb_ * DD + C + 1];
            *reinterpret_cast<__half2*>(&g_AO[(size_t)(bb_ * 2 + qi) * 256 + C]) =
                __floats2half2_rn((acc[nt][2 * half_]     + b0f) * a0 + s0,
                                  (acc[nt][2 * half_ + 1] + b1f) * a1 + s1);
        }
    }
}

// =====================================================================
// final: O projection (gemm32 mode 1)
// =====================================================================
__global__ void __launch_bounds__(256)
final_kernel(const float* __restrict__ bo, float* __restrict__ out,
             const float* __restrict__ X)
{
    extern __shared__ __align__(16) char sm[];
    gemm32_body(1, bo, out, X, (blockIdx.x & 63) * 32, blockIdx.x >> 6,
                sm, smem_u32(sm));
}

// =====================================================================
extern "C" void kernel_launch(void* const* d_in, const int* in_sizes, int n_in,
                              void* d_out, int out_size)
{
    (void)in_sizes; (void)n_in; (void)out_size;
    const float* X      = (const float*)d_in[0];
    const float* EF     = (const float*)d_in[1];
    const float* Wq     = (const float*)d_in[2];
    const float* bq     = (const float*)d_in[3];
    const float* Wk     = (const float*)d_in[4];
    const float* bk     = (const float*)d_in[5];
    const float* Wv     = (const float*)d_in[6];
    const float* bv     = (const float*)d_in[7];
    const float* Wo     = (const float*)d_in[8];
    const float* bo     = (const float*)d_in[9];
    const float* Wbias  = (const float*)d_in[10];
    const float* bbias  = (const float*)d_in[11];
    const float* Wgate  = (const float*)d_in[12];
    const float* bgate  = (const float*)d_in[13];
    const float* Wscale = (const float*)d_in[14];
    const float* bscale = (const float*)d_in[15];
    const float* Wshift = (const float*)d_in[16];
    const float* bshift = (const float*)d_in[17];
    const float* Whead  = (const float*)d_in[18];
    const float* bhead  = (const float*)d_in[19];
    float* out = (float*)d_out;

    cudaFuncSetAttribute(mid1_kernel,  cudaFuncAttributeMaxDynamicSharedMemorySize, G32_SMEM);
    cudaFuncSetAttribute(fused_kernel, cudaFuncAttributeMaxDynamicSharedMemorySize, FX_SMEM);
    cudaFuncSetAttribute(aoh_kernel,   cudaFuncAttributeMaxDynamicSharedMemorySize, AO_SMEM);
    cudaFuncSetAttribute(final_kernel, cudaFuncAttributeMaxDynamicSharedMemorySize, G32_SMEM);

    prep_kernel<<<608, 256>>>(Wk, Wv, Wq, Wo, Wgate, Wscale, Wshift, EF);
    mid1_kernel<<<224, 256, G32_SMEM>>>(bgate, bscale, bshift, bq, X);
    mid2_kernel<<<1280, 256>>>(EF, Wbias, bbias, Whead, bhead, bk);
    fused_kernel<<<1024, 256, FX_SMEM>>>(X);
    aoh_kernel<<<256, 256, AO_SMEM>>>(bv);
    final_kernel<<<128, 256, G32_SMEM>>>(bo, out, X);
}